// round 7
// baseline (speedup 1.0000x reference)
#include <cuda_runtime.h>
#include <cuda_fp16.h>
#include <math.h>
#include <cstdint>

#define T_STEPS 21
#define B 4096
#define H 1024
#define E 50
#define V 96
#define G4 4096  // 4*H

#define DST 6                 // pipeline stages
#define STAGE_BYTES 16384     // A 8KB + B 8KB per k32 stage (int8 2-digit)
#define SMEM_TOTAL (DST * STAGE_BYTES)
#define NSTG 32               // 1024 / 32

// ---------------- device globals (no allocs allowed) ----------------
// Packed int8 layout per row (1024 k): per k32 group kg (32 groups, 64B each),
// chunk tq (4 per group, 16B): [hi quad k=4tq..4tq+3][hi quad k=16+4tq..][lo quad][lo quad]
// byte offset = row*2048 + kg*64 + tq*16 + part*4 + b   (lo at +8)
__device__ __align__(256) float  g_proj[V * G4];               // [v][u*4+gate]
__device__ __align__(256) int8_t g_Wp[(size_t)G4 * 2048];      // W_hh: N-perm + pack, 2 digits
__device__ __align__(256) int8_t g_hs[2][(size_t)B * 2048];    // h digits, ping-pong
__device__ __align__(256) float  g_c[B * H];                   // cell state
__device__ __align__(256) float  g_h[(size_t)T_STEPS * B * H]; // all h (out proj)

__device__ __forceinline__ float sigf(float x) { return 1.0f / (1.0f + __expf(-x)); }

__device__ __forceinline__ uint32_t smem_u32(const void* p) {
    uint32_t a;
    asm("{ .reg .u64 t; cvta.to.shared.u64 t, %1; cvt.u32.u64 %0, t; }" : "=r"(a) : "l"(p));
    return a;
}

// D(s32) = A(16x32 row, s8) * B(32x8 col, s8) + D
__device__ __forceinline__ void mma_s8(int* c, uint32_t a0, uint32_t a1,
                                       uint32_t a2, uint32_t a3,
                                       uint32_t b0, uint32_t b1) {
    asm volatile(
        "mma.sync.aligned.m16n8k32.row.col.s32.s8.s8.s32 "
        "{%0,%1,%2,%3}, {%4,%5,%6,%7}, {%8,%9}, {%0,%1,%2,%3};"
        : "+r"(c[0]), "+r"(c[1]), "+r"(c[2]), "+r"(c[3])
        : "r"(a0), "r"(a1), "r"(a2), "r"(a3), "r"(b0), "r"(b1));
}

// packed byte-offset of k index u within a row (hi digit; lo = +8)
__device__ __forceinline__ int pack_off(int u) {
    return ((u >> 5) << 6) + (((u >> 2) & 3) << 4) + (((u >> 4) & 1) << 2) + (u & 3);
}

__device__ __forceinline__ void split2(int q, int8_t& hi, int8_t& lo) {
    int h = (q + 128) >> 8;
    hi = (int8_t)h;
    lo = (int8_t)(q - (h << 8));
}

// ---------------------------------------------------------------------------
__global__ void copy_c0_kernel(const float* __restrict__ c0) {
    int i = blockIdx.x * blockDim.x + threadIdx.x;
    reinterpret_cast<float4*>(g_c)[i] = reinterpret_cast<const float4*>(c0)[i];
}

// h0 -> int8 digits into ping-pong buffer 1, scale 2^11 (|h0| ~ N(0,1))
__global__ void h0_split_kernel(const float* __restrict__ h0) {
    int i = blockIdx.x * blockDim.x + threadIdx.x;   // over B*H
    int m = i >> 10, u = i & 1023;
    int q = __float2int_rn(h0[i] * 2048.0f);
    q = max(-16384, min(16384, q));
    int8_t hi, lo;
    split2(q, hi, lo);
    size_t o = (size_t)m * 2048 + pack_off(u);
    g_hs[1][o] = hi;
    g_hs[1][o + 8] = lo;
}

// proj[v][u*4+gate] = b_ih[g]+b_hh[g] + sum_e emb[v][e]*W_ih[g][e]
__global__ void vocab_proj_kernel(const float* __restrict__ emb,
                                  const float* __restrict__ W_ih,
                                  const float* __restrict__ b_ih,
                                  const float* __restrict__ b_hh) {
    __shared__ float es[E];
    int v = blockIdx.x;
    if (threadIdx.x < E) es[threadIdx.x] = emb[v * E + threadIdx.x];
    __syncthreads();
    for (int g = threadIdx.x; g < G4; g += blockDim.x) {
        float s = b_ih[g] + b_hh[g];
        const float* w = W_ih + g * E;
#pragma unroll
        for (int e = 0; e < E; e++) s += es[e] * w[e];
        int gate = g >> 10;
        int u = g & (H - 1);
        g_proj[v * G4 + u * 4 + gate] = s;
    }
}

// W_hh[gate*H+u][k] -> g_Wp with N-perm + k-pack + 2-digit split, scale 2^19.
// N-perm: n = 16*(u>>2) + 2*(u&3) + 8*(gate>>1) + (gate&1)
__global__ void permW_split_kernel(const float* __restrict__ W_hh) {
    int idx = blockIdx.x * blockDim.x + threadIdx.x;  // over G4*H
    int g = idx >> 10;
    int k = idx & (H - 1);
    int gate = g >> 10, u = g & (H - 1);
    int n = ((u >> 2) << 4) + ((u & 3) << 1) + ((gate >> 1) << 3) + (gate & 1);
    int q = __float2int_rn(W_hh[idx] * 524288.0f);  // |W| <= 2^-5 -> |q| <= 16384
    int8_t hi, lo;
    split2(q, hi, lo);
    size_t o = (size_t)n * 2048 + pack_off(k);
    g_Wp[o] = hi;
    g_Wp[o + 8] = lo;
}

// ---------------------------------------------------------------------------
// LSTM step via mma.sync s8 (m16n8k32), two-digit fixed point, 3 digit-products.
// Block 128x128, 8 warps (2m x 4n), warp tile 64x32, 32 k32 stages.
__global__ __launch_bounds__(256, 1)
void lstm_step_mma(int t, const int* __restrict__ ids_full, float s1, float s2) {
    extern __shared__ __align__(128) uint8_t smem[];
    const uint32_t sb = smem_u32(smem);

    const int tid = threadIdx.x;
    const int wid = tid >> 5;
    const int lane = tid & 31;
    const int gq = lane >> 2;      // groupID
    const int tq = lane & 3;
    const int wm = wid >> 2;       // 0..1
    const int wn = wid & 3;        // 0..3
    const int m0 = blockIdx.y * 128;
    const int n0 = blockIdx.x * 128;

    const int8_t* __restrict__ Asrc = g_hs[(t & 1) ^ 1];
    const int8_t* __restrict__ Bsrc = g_Wp;

    // ---- stage loader: 1024 x 16B chunks (A 512, B 512), 4 per thread ----
    auto load_stage = [&](int s) {
        uint32_t buf = sb + (uint32_t)(s % DST) * STAGE_BYTES;
#pragma unroll
        for (int i = 0; i < 4; i++) {
            int c = tid + (i << 8);
            int isB = c >> 9;
            int cc = c & 511;
            int row = cc >> 2, tt = cc & 3;
            const int8_t* src = isB
                ? (Bsrc + (size_t)(n0 + row) * 2048 + s * 64 + tt * 16)
                : (Asrc + (size_t)(m0 + row) * 2048 + s * 64 + tt * 16);
            uint32_t dst = buf + (uint32_t)(isB << 13) + (uint32_t)(row * 64 + tt * 16);
            asm volatile("cp.async.cg.shared.global [%0], [%1], 16;"
                         :: "r"(dst), "l"(src));
        }
        asm volatile("cp.async.commit_group;" ::: "memory");
    };

    int accHH[4][4][4];    // sum A1*B1  (scale 2^16)
    int accMid[4][4][4];   // sum A1*B0 + A0*B1 (scale 2^8)
#pragma unroll
    for (int i = 0; i < 4; i++)
#pragma unroll
        for (int j = 0; j < 4; j++)
#pragma unroll
            for (int k = 0; k < 4; k++) { accHH[i][j][k] = 0; accMid[i][j][k] = 0; }

    // prologue
#pragma unroll
    for (int s = 0; s < DST - 1; s++) load_stage(s);

    for (int s = 0; s < NSTG; ++s) {
        asm volatile("cp.async.wait_group %0;" :: "n"(DST - 2) : "memory");
        __syncthreads();

        const uint8_t* buf = smem + (s % DST) * STAGE_BYTES;

        uint4 Bf[4];
#pragma unroll
        for (int ni = 0; ni < 4; ni++) {
            int row = 32 * wn + 8 * ni + gq;
            Bf[ni] = *reinterpret_cast<const uint4*>(buf + 8192 + row * 64 + tq * 16);
        }
#pragma unroll
        for (int mi = 0; mi < 4; mi++) {
            int rowa = 64 * wm + 16 * mi + gq;
            uint4 Ar0 = *reinterpret_cast<const uint4*>(buf + rowa * 64 + tq * 16);
            uint4 Ar1 = *reinterpret_cast<const uint4*>(buf + (rowa + 8) * 64 + tq * 16);
#pragma unroll
            for (int ni = 0; ni < 4; ni++) {
                mma_s8(accHH[mi][ni],  Ar0.x, Ar1.x, Ar0.y, Ar1.y, Bf[ni].x, Bf[ni].y);
                mma_s8(accMid[mi][ni], Ar0.z, Ar1.z, Ar0.w, Ar1.w, Bf[ni].x, Bf[ni].y);
                mma_s8(accMid[mi][ni], Ar0.x, Ar1.x, Ar0.y, Ar1.y, Bf[ni].z, Bf[ni].w);
            }
        }

        if (s + DST - 1 < NSTG) load_stage(s + DST - 1);
        else asm volatile("cp.async.commit_group;" ::: "memory");
    }

    // ---- fused LSTM epilogue (each thread owns whole units) ----
    const int* __restrict__ ids = ids_full + t * B;
    float* __restrict__ hout = g_h + (size_t)t * B * H;
    int8_t* __restrict__ hdst = g_hs[t & 1];

#pragma unroll
    for (int mi = 0; mi < 4; mi++) {
#pragma unroll
        for (int rsel = 0; rsel < 2; rsel++) {
            int m = m0 + 64 * wm + 16 * mi + 8 * rsel + gq;
            int id = __ldg(&ids[m]);
            const float4* __restrict__ pv =
                reinterpret_cast<const float4*>(g_proj + (size_t)id * G4);
#pragma unroll
            for (int p = 0; p < 2; p++) {
                int u = ((n0 + 32 * wn + 16 * p) >> 2) + tq;
                float4 P = pv[u];
                int ai = 2 * rsel;
                float pre_i = (float)accHH[mi][2*p  ][ai  ] * s1
                            + (float)accMid[mi][2*p  ][ai  ] * s2 + P.x;
                float pre_f = (float)accHH[mi][2*p  ][ai+1] * s1
                            + (float)accMid[mi][2*p  ][ai+1] * s2 + P.y;
                float pre_g = (float)accHH[mi][2*p+1][ai  ] * s1
                            + (float)accMid[mi][2*p+1][ai  ] * s2 + P.z;
                float pre_o = (float)accHH[mi][2*p+1][ai+1] * s1
                            + (float)accMid[mi][2*p+1][ai+1] * s2 + P.w;
                size_t cx = (size_t)m * H + u;
                float c = sigf(pre_f) * g_c[cx] + sigf(pre_i) * tanhf(pre_g);
                g_c[cx] = c;
                float h = sigf(pre_o) * tanhf(c);
                hout[cx] = h;
                int q = __float2int_rn(h * 16384.0f);  // |h| < 1 -> |q| <= 16384
                int8_t hh, hl;
                split2(q, hh, hl);
                size_t o = (size_t)m * 2048 + pack_off(u);
                hdst[o] = hh;
                hdst[o + 8] = hl;
            }
        }
    }
}

// ---------------------------------------------------------------------------
// scores[m][v] = h_ts[m] . W_out[v] + b_out[v];  M=86016, N=96, K=1024
__global__ __launch_bounds__(256, 2)
void out_proj_kernel(const float* __restrict__ W_out,
                     const float* __restrict__ b_out,
                     float* __restrict__ scores) {
    __shared__ float As[32][132];
    __shared__ float Ws[32][100];

    const int tid = threadIdx.x;
    const int m0 = blockIdx.x * 128;
    const int tm = tid >> 4, tn = tid & 15;

    float acc[8][6];
#pragma unroll
    for (int i = 0; i < 8; i++)
#pragma unroll
        for (int j = 0; j < 6; j++) acc[i][j] = 0.0f;

    float4 aR[4], wR[3];
#pragma unroll
    for (int i = 0; i < 4; i++) {
        int f4i = tid + (i << 8);
        int row = f4i >> 3, kc = (f4i & 7) << 2;
        aR[i] = *reinterpret_cast<const float4*>(g_h + (size_t)(m0 + row) * H + kc);
    }
#pragma unroll
    for (int i = 0; i < 3; i++) {
        int f4i = tid + (i << 8);
        int vrow = f4i >> 3, kc = (f4i & 7) << 2;
        wR[i] = *reinterpret_cast<const float4*>(W_out + (size_t)vrow * H + kc);
    }

    for (int kt = 0; kt < 32; ++kt) {
#pragma unroll
        for (int i = 0; i < 4; i++) {
            int f4i = tid + (i << 8);
            int row = f4i >> 3, kc = (f4i & 7) << 2;
            As[kc + 0][row] = aR[i].x; As[kc + 1][row] = aR[i].y;
            As[kc + 2][row] = aR[i].z; As[kc + 3][row] = aR[i].w;
        }
#pragma unroll
        for (int i = 0; i < 3; i++) {
            int f4i = tid + (i << 8);
            int vrow = f4i >> 3, kc = (f4i & 7) << 2;
            Ws[kc + 0][vrow] = wR[i].x; Ws[kc + 1][vrow] = wR[i].y;
            Ws[kc + 2][vrow] = wR[i].z; Ws[kc + 3][vrow] = wR[i].w;
        }
        __syncthreads();
        if (kt < 31) {
            int ko = (kt + 1) << 5;
#pragma unroll
            for (int i = 0; i < 4; i++) {
                int f4i = tid + (i << 8);
                int row = f4i >> 3, kc = (f4i & 7) << 2;
                aR[i] = *reinterpret_cast<const float4*>(g_h + (size_t)(m0 + row) * H + ko + kc);
            }
#pragma unroll
            for (int i = 0; i < 3; i++) {
                int f4i = tid + (i << 8);
                int vrow = f4i >> 3, kc = (f4i & 7) << 2;
                wR[i] = *reinterpret_cast<const float4*>(W_out + (size_t)vrow * H + ko + kc);
            }
        }
#pragma unroll
        for (int kk = 0; kk < 32; ++kk) {
            float a[8], b[6];
            *reinterpret_cast<float4*>(a)     = *reinterpret_cast<const float4*>(&As[kk][tm << 3]);
            *reinterpret_cast<float4*>(a + 4) = *reinterpret_cast<const float4*>(&As[kk][(tm << 3) + 4]);
#pragma unroll
            for (int j = 0; j < 6; j++) b[j] = Ws[kk][tn * 6 + j];
#pragma unroll
            for (int i = 0; i < 8; i++)
#pragma unroll
                for (int j = 0; j < 6; j++) acc[i][j] += a[i] * b[j];
        }
        __syncthreads();
    }

#pragma unroll
    for (int r = 0; r < 8; r++) {
        int m = m0 + (tm << 3) + r;
#pragma unroll
        for (int j = 0; j < 6; j++) {
            int v = tn * 6 + j;
            scores[(size_t)m * V + v] = acc[r][j] + __ldg(&b_out[v]);
        }
    }
}

// ---------------------------------------------------------------------------
__global__ void tail_kernel(float* __restrict__ out) {
    int i = blockIdx.x * blockDim.x + threadIdx.x;
    float4* oh = reinterpret_cast<float4*>(out + (size_t)T_STEPS * B * V);
    float4* oc = oh + (B * H / 4);
    oh[i] = reinterpret_cast<const float4*>(g_h + (size_t)(T_STEPS - 1) * B * H)[i];
    oc[i] = reinterpret_cast<const float4*>(g_c)[i];
}

// ---------------------------------------------------------------------------
extern "C" void kernel_launch(void* const* d_in, const int* in_sizes, int n_in,
                              void* d_out, int out_size) {
    const int*   ids   = (const int*)  d_in[0];
    const float* h0    = (const float*)d_in[1];
    const float* c0    = (const float*)d_in[2];
    const float* emb   = (const float*)d_in[3];
    const float* W_ih  = (const float*)d_in[4];
    const float* W_hh  = (const float*)d_in[5];
    const float* b_ih  = (const float*)d_in[6];
    const float* b_hh  = (const float*)d_in[7];
    const float* W_out = (const float*)d_in[8];
    const float* b_out = (const float*)d_in[9];
    float* out = (float*)d_out;

    cudaFuncSetAttribute(lstm_step_mma, cudaFuncAttributeMaxDynamicSharedMemorySize,
                         SMEM_TOTAL);

    copy_c0_kernel<<<B * H / 4 / 256, 256>>>(c0);
    h0_split_kernel<<<B * H / 256, 256>>>(h0);
    vocab_proj_kernel<<<V, 256>>>(emb, W_ih, b_ih, b_hh);
    permW_split_kernel<<<G4 * H / 256, 256>>>(W_hh);

    dim3 gemm_grid(G4 / 128, B / 128);  // 32 x 32 = 1024 CTAs
    for (int t = 0; t < T_STEPS; ++t) {
        // scales: pre = HH * 2^(16-sh-sw) + MID * 2^(8-sh-sw); sw=19, sh=11 (t=0) / 14
        float s1 = (t == 0) ? 6.103515625e-05f    : 7.62939453125e-06f;  // 2^-14 / 2^-17
        float s2 = (t == 0) ? 2.38418579101562e-07f : 2.98023223876953e-08f; // 2^-22 / 2^-25
        lstm_step_mma<<<gemm_grid, 256, SMEM_TOTAL>>>(t, ids, s1, s2);
    }

    out_proj_kernel<<<(T_STEPS * B) / 128, 256>>>(W_out, b_out, out);
    tail_kernel<<<B * H / 4 / 256, 256>>>(out);
}

// round 8
// speedup vs baseline: 3.7704x; 3.7704x over previous
#include <cuda_runtime.h>
#include <cuda_fp16.h>
#include <math.h>
#include <cstdint>

#define T_STEPS 21
#define B 4096
#define H 1024
#define E 50
#define V 96
#define G4 4096  // 4*H

#define DST 6                 // pipeline stages
#define STAGE_BYTES 12288     // A 8KB (hi+lo) + B 4KB (hi only) per k16 stage
#define SMEM_TOTAL (DST * STAGE_BYTES)
#define INV2048 (1.0f / 2048.0f)

// ---------------- device globals (no allocs allowed) ----------------
// A pack (g_hs), per row of 1024 k: per k16 group kg, per t (4): 16B chunk =
// [hi pair q=t][hi pair q=t+4][lo pair q=t][lo pair q=t+4]
// half offset = row*2048 + kg*32 + t*8 + ps*2 + b (+4 for lo), q = t + 4*ps
// B pack (g_Wph), hi only: half offset = row*1024 + kg*16 + t*4 + ps*2 + b
__device__ __align__(256) float  g_proj[V * G4];              // [v][u*4+gate]
__device__ __align__(256) __half g_Wph[(size_t)G4 * 1024];    // W_hh: N-perm + k-pack, hi
__device__ __align__(256) __half g_hs[2][(size_t)B * 2048];   // h split, ping-pong
__device__ __align__(256) float  g_c[B * H];                  // cell state
__device__ __align__(256) float  g_h[(size_t)T_STEPS * B * H];// all h (out proj)

__device__ __forceinline__ float sigf(float x) { return 1.0f / (1.0f + __expf(-x)); }

__device__ __forceinline__ uint32_t smem_u32(const void* p) {
    uint32_t a;
    asm("{ .reg .u64 t; cvta.to.shared.u64 t, %1; cvt.u32.u64 %0, t; }" : "=r"(a) : "l"(p));
    return a;
}

// D(f32) = A(16x16 row, fp16) * B(16x8 col, fp16) + D
__device__ __forceinline__ void mma_f16_f32(float* c, uint32_t a0, uint32_t a1,
                                            uint32_t a2, uint32_t a3,
                                            uint32_t b0, uint32_t b1) {
    asm volatile(
        "mma.sync.aligned.m16n8k16.row.col.f32.f16.f16.f32 "
        "{%0,%1,%2,%3}, {%4,%5,%6,%7}, {%8,%9}, {%0,%1,%2,%3};"
        : "+f"(c[0]), "+f"(c[1]), "+f"(c[2]), "+f"(c[3])
        : "r"(a0), "r"(a1), "r"(a2), "r"(a3), "r"(b0), "r"(b1));
}

// packed half-offset of k index u within an A row (hi slot; lo = +4)
__device__ __forceinline__ int pack_off(int u) {
    int kg = u >> 4, kl = u & 15, q = kl >> 1, b = kl & 1;
    int t = q & 3, ps = q >> 2;
    return kg * 32 + t * 8 + ps * 2 + b;
}
// packed half-offset of k index within a B (hi-only) row
__device__ __forceinline__ int pack_off_b(int u) {
    int kg = u >> 4, kl = u & 15, q = kl >> 1, b = kl & 1;
    int t = q & 3, ps = q >> 2;
    return kg * 16 + t * 4 + ps * 2 + b;
}

// ---------------------------------------------------------------------------
__global__ void copy_c0_kernel(const float* __restrict__ c0) {
    int i = blockIdx.x * blockDim.x + threadIdx.x;
    reinterpret_cast<float4*>(g_c)[i] = reinterpret_cast<const float4*>(c0)[i];
}

// h0 -> split into ping-pong buffer 1 (step 0 reads (0&1)^1 = 1)
__global__ void h0_split_kernel(const float* __restrict__ h0) {
    int i = blockIdx.x * blockDim.x + threadIdx.x;   // over B*H
    int m = i >> 10, u = i & 1023;
    float x = h0[i];
    __half hh = __float2half_rn(x);
    __half hl = __float2half_rn((x - __half2float(hh)) * 2048.0f);
    size_t o = (size_t)m * 2048 + pack_off(u);
    g_hs[1][o] = hh;
    g_hs[1][o + 4] = hl;
}

// proj[v][u*4+gate] = b_ih[g]+b_hh[g] + sum_e emb[v][e]*W_ih[g][e]
__global__ void vocab_proj_kernel(const float* __restrict__ emb,
                                  const float* __restrict__ W_ih,
                                  const float* __restrict__ b_ih,
                                  const float* __restrict__ b_hh) {
    __shared__ float es[E];
    int v = blockIdx.x;
    if (threadIdx.x < E) es[threadIdx.x] = emb[v * E + threadIdx.x];
    __syncthreads();
    for (int g = threadIdx.x; g < G4; g += blockDim.x) {
        float s = b_ih[g] + b_hh[g];
        const float* w = W_ih + g * E;
#pragma unroll
        for (int e = 0; e < E; e++) s += es[e] * w[e];
        int gate = g >> 10;
        int u = g & (H - 1);
        g_proj[v * G4 + u * 4 + gate] = s;
    }
}

// W_hh[gate*H+u][k] -> g_Wph with N-perm + k-pack, fp16 hi only.
// N-perm: n = 16*(u>>2) + 2*(u&3) + 8*(gate>>1) + (gate&1)
__global__ void permW_hi_kernel(const float* __restrict__ W_hh) {
    int idx = blockIdx.x * blockDim.x + threadIdx.x;  // over G4*H
    int g = idx >> 10;
    int k = idx & (H - 1);
    int gate = g >> 10, u = g & (H - 1);
    int n = ((u >> 2) << 4) + ((u & 3) << 1) + ((gate >> 1) << 3) + (gate & 1);
    g_Wph[(size_t)n * 1024 + pack_off_b(k)] = __float2half_rn(W_hh[idx]);
}

// ---------------------------------------------------------------------------
// LSTM step via mma.sync fp16: pre = (Ahi + Alo/2048) * Bhi. Block 128x128,
// 8 warps (2m x 4n), warp tile 64x32, 64 k16 stages, 6-deep cp.async pipeline.
__global__ __launch_bounds__(256, 1)
void lstm_step_mma(int t, const int* __restrict__ ids_full) {
    extern __shared__ __align__(128) uint8_t smem[];
    const uint32_t sb = smem_u32(smem);

    const int tid = threadIdx.x;
    const int wid = tid >> 5;
    const int lane = tid & 31;
    const int gq = lane >> 2;      // groupID
    const int tq = lane & 3;
    const int wm = wid >> 2;       // 0..1
    const int wn = wid & 3;        // 0..3
    const int m0 = blockIdx.y * 128;
    const int n0 = blockIdx.x * 128;

    const __half* __restrict__ Asrc = g_hs[(t & 1) ^ 1];
    const __half* __restrict__ Bsrc = g_Wph;

    // ---- stage loader: A 512 x 16B chunks (2/thr), B 256 x 16B chunks (1/thr) --
    auto load_stage = [&](int s) {
        uint32_t buf = sb + (uint32_t)(s % DST) * STAGE_BYTES;
#pragma unroll
        for (int i = 0; i < 2; i++) {
            int c = tid + (i << 8);
            int row = c >> 2, tt = c & 3;
            const __half* src = Asrc + (size_t)(m0 + row) * 2048 + s * 32 + tt * 8;
            uint32_t dst = buf + (uint32_t)(row * 64 + tt * 16);
            asm volatile("cp.async.cg.shared.global [%0], [%1], 16;"
                         :: "r"(dst), "l"(src));
        }
        {
            int row = tid >> 1, tt = tid & 1;
            const __half* src = Bsrc + (size_t)(n0 + row) * 1024 + s * 16 + tt * 8;
            uint32_t dst = buf + 8192u + (uint32_t)(row * 32 + tt * 16);
            asm volatile("cp.async.cg.shared.global [%0], [%1], 16;"
                         :: "r"(dst), "l"(src));
        }
        asm volatile("cp.async.commit_group;" ::: "memory");
    };

    float accM[4][4][4];   // Ahi*Bhi
    float accC[4][4][4];   // Alo'*Bhi (x 1/2048)
#pragma unroll
    for (int i = 0; i < 4; i++)
#pragma unroll
        for (int j = 0; j < 4; j++)
#pragma unroll
            for (int k = 0; k < 4; k++) { accM[i][j][k] = 0.f; accC[i][j][k] = 0.f; }

    // prologue
#pragma unroll
    for (int s = 0; s < DST - 1; s++) load_stage(s);

    for (int s = 0; s < 64; ++s) {
        asm volatile("cp.async.wait_group %0;" :: "n"(DST - 2) : "memory");
        __syncthreads();

        const uint8_t* buf = smem + (s % DST) * STAGE_BYTES;

        uint2 Bf[4];
#pragma unroll
        for (int ni = 0; ni < 4; ni++) {
            int row = 32 * wn + 8 * ni + gq;
            Bf[ni] = *reinterpret_cast<const uint2*>(buf + 8192 + row * 32 + tq * 8);
        }
#pragma unroll
        for (int mi = 0; mi < 4; mi++) {
            int rowa = 64 * wm + 16 * mi + gq;
            uint4 Ar0 = *reinterpret_cast<const uint4*>(buf + rowa * 64 + tq * 16);
            uint4 Ar1 = *reinterpret_cast<const uint4*>(buf + (rowa + 8) * 64 + tq * 16);
#pragma unroll
            for (int ni = 0; ni < 4; ni++) {
                mma_f16_f32(accM[mi][ni], Ar0.x, Ar1.x, Ar0.y, Ar1.y, Bf[ni].x, Bf[ni].y);
                mma_f16_f32(accC[mi][ni], Ar0.z, Ar1.z, Ar0.w, Ar1.w, Bf[ni].x, Bf[ni].y);
            }
        }

        if (s + DST - 1 < 64) load_stage(s + DST - 1);
        else asm volatile("cp.async.commit_group;" ::: "memory");
    }

    // ---- fused LSTM epilogue (each thread owns whole units) ----
    const int* __restrict__ ids = ids_full + t * B;
    float* __restrict__ hout = g_h + (size_t)t * B * H;
    __half* __restrict__ hdst = g_hs[t & 1];

#pragma unroll
    for (int mi = 0; mi < 4; mi++) {
#pragma unroll
        for (int rsel = 0; rsel < 2; rsel++) {
            int m = m0 + 64 * wm + 16 * mi + 8 * rsel + gq;
            int id = __ldg(&ids[m]);
            const float4* __restrict__ pv =
                reinterpret_cast<const float4*>(g_proj + (size_t)id * G4);
#pragma unroll
            for (int p = 0; p < 2; p++) {
                int u = ((n0 + 32 * wn + 16 * p) >> 2) + tq;
                float4 P = pv[u];
                int ai = 2 * rsel;
                float pre_i = accM[mi][2*p  ][ai  ] + accC[mi][2*p  ][ai  ] * INV2048 + P.x;
                float pre_f = accM[mi][2*p  ][ai+1] + accC[mi][2*p  ][ai+1] * INV2048 + P.y;
                float pre_g = accM[mi][2*p+1][ai  ] + accC[mi][2*p+1][ai  ] * INV2048 + P.z;
                float pre_o = accM[mi][2*p+1][ai+1] + accC[mi][2*p+1][ai+1] * INV2048 + P.w;
                size_t cx = (size_t)m * H + u;
                float c = sigf(pre_f) * g_c[cx] + sigf(pre_i) * tanhf(pre_g);
                g_c[cx] = c;
                float h = sigf(pre_o) * tanhf(c);
                hout[cx] = h;
                __half hh = __float2half_rn(h);
                __half hl = __float2half_rn((h - __half2float(hh)) * 2048.0f);
                size_t o = (size_t)m * 2048 + pack_off(u);
                hdst[o] = hh;
                hdst[o + 4] = hl;
            }
        }
    }
}

// ---------------------------------------------------------------------------
// scores[m][v] = h_ts[m] . W_out[v] + b_out[v];  M=86016, N=96, K=1024
__global__ __launch_bounds__(256, 2)
void out_proj_kernel(const float* __restrict__ W_out,
                     const float* __restrict__ b_out,
                     float* __restrict__ scores) {
    __shared__ float As[32][132];
    __shared__ float Ws[32][100];

    const int tid = threadIdx.x;
    const int m0 = blockIdx.x * 128;
    const int tm = tid >> 4, tn = tid & 15;

    float acc[8][6];
#pragma unroll
    for (int i = 0; i < 8; i++)
#pragma unroll
        for (int j = 0; j < 6; j++) acc[i][j] = 0.0f;

    float4 aR[4], wR[3];
#pragma unroll
    for (int i = 0; i < 4; i++) {
        int f4i = tid + (i << 8);
        int row = f4i >> 3, kc = (f4i & 7) << 2;
        aR[i] = *reinterpret_cast<const float4*>(g_h + (size_t)(m0 + row) * H + kc);
    }
#pragma unroll
    for (int i = 0; i < 3; i++) {
        int f4i = tid + (i << 8);
        int vrow = f4i >> 3, kc = (f4i & 7) << 2;
        wR[i] = *reinterpret_cast<const float4*>(W_out + (size_t)vrow * H + kc);
    }

    for (int kt = 0; kt < 32; ++kt) {
#pragma unroll
        for (int i = 0; i < 4; i++) {
            int f4i = tid + (i << 8);
            int row = f4i >> 3, kc = (f4i & 7) << 2;
            As[kc + 0][row] = aR[i].x; As[kc + 1][row] = aR[i].y;
            As[kc + 2][row] = aR[i].z; As[kc + 3][row] = aR[i].w;
        }
#pragma unroll
        for (int i = 0; i < 3; i++) {
            int f4i = tid + (i << 8);
            int vrow = f4i >> 3, kc = (f4i & 7) << 2;
            Ws[kc + 0][vrow] = wR[i].x; Ws[kc + 1][vrow] = wR[i].y;
            Ws[kc + 2][vrow] = wR[i].z; Ws[kc + 3][vrow] = wR[i].w;
        }
        __syncthreads();
        if (kt < 31) {
            int ko = (kt + 1) << 5;
#pragma unroll
            for (int i = 0; i < 4; i++) {
                int f4i = tid + (i << 8);
                int row = f4i >> 3, kc = (f4i & 7) << 2;
                aR[i] = *reinterpret_cast<const float4*>(g_h + (size_t)(m0 + row) * H + ko + kc);
            }
#pragma unroll
            for (int i = 0; i < 3; i++) {
                int f4i = tid + (i << 8);
                int vrow = f4i >> 3, kc = (f4i & 7) << 2;
                wR[i] = *reinterpret_cast<const float4*>(W_out + (size_t)vrow * H + ko + kc);
            }
        }
#pragma unroll
        for (int kk = 0; kk < 32; ++kk) {
            float a[8], b[6];
            *reinterpret_cast<float4*>(a)     = *reinterpret_cast<const float4*>(&As[kk][tm << 3]);
            *reinterpret_cast<float4*>(a + 4) = *reinterpret_cast<const float4*>(&As[kk][(tm << 3) + 4]);
#pragma unroll
            for (int j = 0; j < 6; j++) b[j] = Ws[kk][tn * 6 + j];
#pragma unroll
            for (int i = 0; i < 8; i++)
#pragma unroll
                for (int j = 0; j < 6; j++) acc[i][j] += a[i] * b[j];
        }
        __syncthreads();
    }

#pragma unroll
    for (int r = 0; r < 8; r++) {
        int m = m0 + (tm << 3) + r;
#pragma unroll
        for (int j = 0; j < 6; j++) {
            int v = tn * 6 + j;
            scores[(size_t)m * V + v] = acc[r][j] + __ldg(&b_out[v]);
        }
    }
}

// ---------------------------------------------------------------------------
__global__ void tail_kernel(float* __restrict__ out) {
    int i = blockIdx.x * blockDim.x + threadIdx.x;
    float4* oh = reinterpret_cast<float4*>(out + (size_t)T_STEPS * B * V);
    float4* oc = oh + (B * H / 4);
    oh[i] = reinterpret_cast<const float4*>(g_h + (size_t)(T_STEPS - 1) * B * H)[i];
    oc[i] = reinterpret_cast<const float4*>(g_c)[i];
}

// ---------------------------------------------------------------------------
extern "C" void kernel_launch(void* const* d_in, const int* in_sizes, int n_in,
                              void* d_out, int out_size) {
    const int*   ids   = (const int*)  d_in[0];
    const float* h0    = (const float*)d_in[1];
    const float* c0    = (const float*)d_in[2];
    const float* emb   = (const float*)d_in[3];
    const float* W_ih  = (const float*)d_in[4];
    const float* W_hh  = (const float*)d_in[5];
    const float* b_ih  = (const float*)d_in[6];
    const float* b_hh  = (const float*)d_in[7];
    const float* W_out = (const float*)d_in[8];
    const float* b_out = (const float*)d_in[9];
    float* out = (float*)d_out;

    cudaFuncSetAttribute(lstm_step_mma, cudaFuncAttributeMaxDynamicSharedMemorySize,
                         SMEM_TOTAL);

    copy_c0_kernel<<<B * H / 4 / 256, 256>>>(c0);
    h0_split_kernel<<<B * H / 256, 256>>>(h0);
    vocab_proj_kernel<<<V, 256>>>(emb, W_ih, b_ih, b_hh);
    permW_hi_kernel<<<G4 * H / 256, 256>>>(W_hh);

    dim3 gemm_grid(G4 / 128, B / 128);  // 32 x 32 = 1024 CTAs
    for (int t = 0; t < T_STEPS; ++t) {
        lstm_step_mma<<<gemm_grid, 256, SMEM_TOTAL>>>(t, ids);
    }

    out_proj_kernel<<<(T_STEPS * B) / 128, 256>>>(W_out, b_out, out);
    tail_kernel<<<B * H / 4 / 256, 256>>>(out);
}

// round 9
// speedup vs baseline: 7.3932x; 1.9608x over previous
#include <cuda_runtime.h>
#include <cuda_fp16.h>
#include <math.h>
#include <cstdint>

#define T_STEPS 21
#define B 4096
#define H 1024
#define E 50
#define V 96
#define G4 4096  // 4*H

#define DST 6                 // pipeline stages
#define STAGE_BYTES 8192      // A 4KB + B 4KB per k16 stage (fp16 hi-only both sides)
#define SMEM_TOTAL (DST * STAGE_BYTES)

// ---------------- device globals (no allocs allowed) ----------------
// Packed fp16 row layout (1024 k, hi only): per k16 group kg (64B... 32B):
// half offset = row*1024 + kg*16 + t*4 + ps*2 + b, where k = 2*(t+4*ps)+b
__device__ __align__(256) float  g_proj[V * G4];              // [v][u*4+gate]
__device__ __align__(256) __half g_Wph[(size_t)G4 * 1024];    // W_hh: N-perm + k-pack
__device__ __align__(256) __half g_hq[2][(size_t)B * 1024];   // h fp16, ping-pong
__device__ __align__(256) float  g_c[B * H];                  // cell state
__device__ __align__(256) float  g_h[(size_t)T_STEPS * B * H];// all h (out proj)

__device__ __forceinline__ float sigf(float x) { return 1.0f / (1.0f + __expf(-x)); }

__device__ __forceinline__ uint32_t smem_u32(const void* p) {
    uint32_t a;
    asm("{ .reg .u64 t; cvta.to.shared.u64 t, %1; cvt.u32.u64 %0, t; }" : "=r"(a) : "l"(p));
    return a;
}

// D(f32) = A(16x16 row, fp16) * B(16x8 col, fp16) + D
__device__ __forceinline__ void mma_f16_f32(float* c, uint32_t a0, uint32_t a1,
                                            uint32_t a2, uint32_t a3,
                                            uint32_t b0, uint32_t b1) {
    asm volatile(
        "mma.sync.aligned.m16n8k16.row.col.f32.f16.f16.f32 "
        "{%0,%1,%2,%3}, {%4,%5,%6,%7}, {%8,%9}, {%0,%1,%2,%3};"
        : "+f"(c[0]), "+f"(c[1]), "+f"(c[2]), "+f"(c[3])
        : "r"(a0), "r"(a1), "r"(a2), "r"(a3), "r"(b0), "r"(b1));
}

// packed half-offset of k index u within a row
__device__ __forceinline__ int pack_off(int u) {
    int kg = u >> 4, kl = u & 15, q = kl >> 1, b = kl & 1;
    int t = q & 3, ps = q >> 2;
    return kg * 16 + t * 4 + ps * 2 + b;
}

// ---------------------------------------------------------------------------
__global__ void copy_c0_kernel(const float* __restrict__ c0) {
    int i = blockIdx.x * blockDim.x + threadIdx.x;
    reinterpret_cast<float4*>(g_c)[i] = reinterpret_cast<const float4*>(c0)[i];
}

// h0 -> fp16 into ping-pong buffer 1 (step 0 reads (0&1)^1 = 1)
__global__ void h0_q_kernel(const float* __restrict__ h0) {
    int i = blockIdx.x * blockDim.x + threadIdx.x;   // over B*H
    int m = i >> 10, u = i & 1023;
    g_hq[1][(size_t)m * 1024 + pack_off(u)] = __float2half_rn(h0[i]);
}

// proj[v][u*4+gate] = b_ih[g]+b_hh[g] + sum_e emb[v][e]*W_ih[g][e]
__global__ void vocab_proj_kernel(const float* __restrict__ emb,
                                  const float* __restrict__ W_ih,
                                  const float* __restrict__ b_ih,
                                  const float* __restrict__ b_hh) {
    __shared__ float es[E];
    int v = blockIdx.x;
    if (threadIdx.x < E) es[threadIdx.x] = emb[v * E + threadIdx.x];
    __syncthreads();
    for (int g = threadIdx.x; g < G4; g += blockDim.x) {
        float s = b_ih[g] + b_hh[g];
        const float* w = W_ih + g * E;
#pragma unroll
        for (int e = 0; e < E; e++) s += es[e] * w[e];
        int gate = g >> 10;
        int u = g & (H - 1);
        g_proj[v * G4 + u * 4 + gate] = s;
    }
}

// W_hh[gate*H+u][k] -> g_Wph with N-perm + k-pack, fp16.
// N-perm: n = 16*(u>>2) + 2*(u&3) + 8*(gate>>1) + (gate&1)
__global__ void permW_hi_kernel(const float* __restrict__ W_hh) {
    int idx = blockIdx.x * blockDim.x + threadIdx.x;  // over G4*H
    int g = idx >> 10;
    int k = idx & (H - 1);
    int gate = g >> 10, u = g & (H - 1);
    int n = ((u >> 2) << 4) + ((u & 3) << 1) + ((gate >> 1) << 3) + (gate & 1);
    g_Wph[(size_t)n * 1024 + pack_off(k)] = __float2half_rn(W_hh[idx]);
}

// ---------------------------------------------------------------------------
// LSTM step: pre = fp16(h) @ fp16(W)^T, f32 accum. Block 128x128, 8 warps
// (2m x 4n), warp tile 64x32, 64 k16 stages, 6-deep cp.async, 2 CTAs/SM.
__global__ __launch_bounds__(256, 2)
void lstm_step_mma(int t, const int* __restrict__ ids_full) {
    extern __shared__ __align__(128) uint8_t smem[];
    const uint32_t sb = smem_u32(smem);

    const int tid = threadIdx.x;
    const int wid = tid >> 5;
    const int lane = tid & 31;
    const int gq = lane >> 2;      // groupID
    const int tq = lane & 3;
    const int wm = wid >> 2;       // 0..1
    const int wn = wid & 3;        // 0..3
    const int m0 = blockIdx.y * 128;
    const int n0 = blockIdx.x * 128;

    const __half* __restrict__ Asrc = g_hq[(t & 1) ^ 1];
    const __half* __restrict__ Bsrc = g_Wph;

    // ---- stage loader: 512 x 16B chunks (A 256, B 256), 2 per thread ----
    auto load_stage = [&](int s) {
        uint32_t buf = sb + (uint32_t)(s % DST) * STAGE_BYTES;
#pragma unroll
        for (int i = 0; i < 2; i++) {
            int c = tid + (i << 8);
            int isB = c >> 8;
            int cc = c & 255;
            int row = cc >> 1, tt = cc & 1;
            const __half* src = isB
                ? (Bsrc + (size_t)(n0 + row) * 1024 + s * 16 + tt * 8)
                : (Asrc + (size_t)(m0 + row) * 1024 + s * 16 + tt * 8);
            uint32_t dst = buf + (uint32_t)(isB << 12) + (uint32_t)(row * 32 + tt * 16);
            asm volatile("cp.async.cg.shared.global [%0], [%1], 16;"
                         :: "r"(dst), "l"(src));
        }
        asm volatile("cp.async.commit_group;" ::: "memory");
    };

    float accM[4][4][4];
#pragma unroll
    for (int i = 0; i < 4; i++)
#pragma unroll
        for (int j = 0; j < 4; j++)
#pragma unroll
            for (int k = 0; k < 4; k++) accM[i][j][k] = 0.f;

    // prologue
#pragma unroll
    for (int s = 0; s < DST - 1; s++) load_stage(s);

    for (int s = 0; s < 64; ++s) {
        asm volatile("cp.async.wait_group %0;" :: "n"(DST - 2) : "memory");
        __syncthreads();

        const uint8_t* buf = smem + (s % DST) * STAGE_BYTES;

        uint2 Bf[4];
#pragma unroll
        for (int ni = 0; ni < 4; ni++) {
            int row = 32 * wn + 8 * ni + gq;
            Bf[ni] = *reinterpret_cast<const uint2*>(buf + 4096 + row * 32 + tq * 8);
        }
#pragma unroll
        for (int mi = 0; mi < 4; mi++) {
            int rowa = 64 * wm + 16 * mi + gq;
            uint2 A0 = *reinterpret_cast<const uint2*>(buf + rowa * 32 + tq * 8);
            uint2 A1 = *reinterpret_cast<const uint2*>(buf + (rowa + 8) * 32 + tq * 8);
#pragma unroll
            for (int ni = 0; ni < 4; ni++) {
                mma_f16_f32(accM[mi][ni], A0.x, A1.x, A0.y, A1.y, Bf[ni].x, Bf[ni].y);
            }
        }

        if (s + DST - 1 < 64) load_stage(s + DST - 1);
        else asm volatile("cp.async.commit_group;" ::: "memory");
    }

    // ---- fused LSTM epilogue (each thread owns whole units) ----
    const int* __restrict__ ids = ids_full + t * B;
    float* __restrict__ hout = g_h + (size_t)t * B * H;
    __half* __restrict__ hdst = g_hq[t & 1];

#pragma unroll
    for (int mi = 0; mi < 4; mi++) {
#pragma unroll
        for (int rsel = 0; rsel < 2; rsel++) {
            int m = m0 + 64 * wm + 16 * mi + 8 * rsel + gq;
            int id = __ldg(&ids[m]);
            const float4* __restrict__ pv =
                reinterpret_cast<const float4*>(g_proj + (size_t)id * G4);
#pragma unroll
            for (int p = 0; p < 2; p++) {
                int u = ((n0 + 32 * wn + 16 * p) >> 2) + tq;
                float4 P = pv[u];
                int ai = 2 * rsel;
                float pre_i = accM[mi][2*p  ][ai  ] + P.x;
                float pre_f = accM[mi][2*p  ][ai+1] + P.y;
                float pre_g = accM[mi][2*p+1][ai  ] + P.z;
                float pre_o = accM[mi][2*p+1][ai+1] + P.w;
                size_t cx = (size_t)m * H + u;
                float c = sigf(pre_f) * g_c[cx] + sigf(pre_i) * tanhf(pre_g);
                g_c[cx] = c;
                float h = sigf(pre_o) * tanhf(c);
                hout[cx] = h;
                hdst[(size_t)m * 1024 + pack_off(u)] = __float2half_rn(h);
            }
        }
    }
}

// ---------------------------------------------------------------------------
// scores[m][v] = h_ts[m] . W_out[v] + b_out[v];  M=86016, N=96, K=1024
__global__ __launch_bounds__(256, 2)
void out_proj_kernel(const float* __restrict__ W_out,
                     const float* __restrict__ b_out,
                     float* __restrict__ scores) {
    __shared__ float As[32][132];
    __shared__ float Ws[32][100];

    const int tid = threadIdx.x;
    const int m0 = blockIdx.x * 128;
    const int tm = tid >> 4, tn = tid & 15;

    float acc[8][6];
#pragma unroll
    for (int i = 0; i < 8; i++)
#pragma unroll
        for (int j = 0; j < 6; j++) acc[i][j] = 0.0f;

    float4 aR[4], wR[3];
#pragma unroll
    for (int i = 0; i < 4; i++) {
        int f4i = tid + (i << 8);
        int row = f4i >> 3, kc = (f4i & 7) << 2;
        aR[i] = *reinterpret_cast<const float4*>(g_h + (size_t)(m0 + row) * H + kc);
    }
#pragma unroll
    for (int i = 0; i < 3; i++) {
        int f4i = tid + (i << 8);
        int vrow = f4i >> 3, kc = (f4i & 7) << 2;
        wR[i] = *reinterpret_cast<const float4*>(W_out + (size_t)vrow * H + kc);
    }

    for (int kt = 0; kt < 32; ++kt) {
#pragma unroll
        for (int i = 0; i < 4; i++) {
            int f4i = tid + (i << 8);
            int row = f4i >> 3, kc = (f4i & 7) << 2;
            As[kc + 0][row] = aR[i].x; As[kc + 1][row] = aR[i].y;
            As[kc + 2][row] = aR[i].z; As[kc + 3][row] = aR[i].w;
        }
#pragma unroll
        for (int i = 0; i < 3; i++) {
            int f4i = tid + (i << 8);
            int vrow = f4i >> 3, kc = (f4i & 7) << 2;
            Ws[kc + 0][vrow] = wR[i].x; Ws[kc + 1][vrow] = wR[i].y;
            Ws[kc + 2][vrow] = wR[i].z; Ws[kc + 3][vrow] = wR[i].w;
        }
        __syncthreads();
        if (kt < 31) {
            int ko = (kt + 1) << 5;
#pragma unroll
            for (int i = 0; i < 4; i++) {
                int f4i = tid + (i << 8);
                int row = f4i >> 3, kc = (f4i & 7) << 2;
                aR[i] = *reinterpret_cast<const float4*>(g_h + (size_t)(m0 + row) * H + ko + kc);
            }
#pragma unroll
            for (int i = 0; i < 3; i++) {
                int f4i = tid + (i << 8);
                int vrow = f4i >> 3, kc = (f4i & 7) << 2;
                wR[i] = *reinterpret_cast<const float4*>(W_out + (size_t)vrow * H + ko + kc);
            }
        }
#pragma unroll
        for (int kk = 0; kk < 32; ++kk) {
            float a[8], b[6];
            *reinterpret_cast<float4*>(a)     = *reinterpret_cast<const float4*>(&As[kk][tm << 3]);
            *reinterpret_cast<float4*>(a + 4) = *reinterpret_cast<const float4*>(&As[kk][(tm << 3) + 4]);
#pragma unroll
            for (int j = 0; j < 6; j++) b[j] = Ws[kk][tn * 6 + j];
#pragma unroll
            for (int i = 0; i < 8; i++)
#pragma unroll
                for (int j = 0; j < 6; j++) acc[i][j] += a[i] * b[j];
        }
        __syncthreads();
    }

#pragma unroll
    for (int r = 0; r < 8; r++) {
        int m = m0 + (tm << 3) + r;
#pragma unroll
        for (int j = 0; j < 6; j++) {
            int v = tn * 6 + j;
            scores[(size_t)m * V + v] = acc[r][j] + __ldg(&b_out[v]);
        }
    }
}

// ---------------------------------------------------------------------------
__global__ void tail_kernel(float* __restrict__ out) {
    int i = blockIdx.x * blockDim.x + threadIdx.x;
    float4* oh = reinterpret_cast<float4*>(out + (size_t)T_STEPS * B * V);
    float4* oc = oh + (B * H / 4);
    oh[i] = reinterpret_cast<const float4*>(g_h + (size_t)(T_STEPS - 1) * B * H)[i];
    oc[i] = reinterpret_cast<const float4*>(g_c)[i];
}

// ---------------------------------------------------------------------------
extern "C" void kernel_launch(void* const* d_in, const int* in_sizes, int n_in,
                              void* d_out, int out_size) {
    const int*   ids   = (const int*)  d_in[0];
    const float* h0    = (const float*)d_in[1];
    const float* c0    = (const float*)d_in[2];
    const float* emb   = (const float*)d_in[3];
    const float* W_ih  = (const float*)d_in[4];
    const float* W_hh  = (const float*)d_in[5];
    const float* b_ih  = (const float*)d_in[6];
    const float* b_hh  = (const float*)d_in[7];
    const float* W_out = (const float*)d_in[8];
    const float* b_out = (const float*)d_in[9];
    float* out = (float*)d_out;

    cudaFuncSetAttribute(lstm_step_mma, cudaFuncAttributeMaxDynamicSharedMemorySize,
                         SMEM_TOTAL);

    copy_c0_kernel<<<B * H / 4 / 256, 256>>>(c0);
    h0_q_kernel<<<B * H / 256, 256>>>(h0);
    vocab_proj_kernel<<<V, 256>>>(emb, W_ih, b_ih, b_hh);
    permW_hi_kernel<<<G4 * H / 256, 256>>>(W_hh);

    dim3 gemm_grid(G4 / 128, B / 128);  // 32 x 32 = 1024 CTAs
    for (int t = 0; t < T_STEPS; ++t) {
        lstm_step_mma<<<gemm_grid, 256, SMEM_TOTAL>>>(t, ids);
    }

    out_proj_kernel<<<(T_STEPS * B) / 128, 256>>>(W_out, b_out, out);
    tail_kernel<<<B * H / 4 / 256, 256>>>(out);
}

// round 10
// speedup vs baseline: 8.0693x; 1.0914x over previous
#include <cuda_runtime.h>
#include <cuda_fp16.h>
#include <math.h>
#include <cstdint>

#define T_STEPS 21
#define B 4096
#define H 1024
#define E 50
#define V 96
#define G4 4096  // 4*H

#define DST 6                 // pipeline stages
#define STAGE_BYTES 8192      // A 4KB + B 4KB (lstm) / A 4KB + B 3KB (proj)
#define SMEM_TOTAL (DST * STAGE_BYTES)

// ---------------- device globals (no allocs allowed) ----------------
// Packed fp16 row layout (1024 k): half offset = row*1024 + pack_off(k)
__device__ __align__(256) float  g_proj[V * G4];                 // [v][u*4+gate]
__device__ __align__(256) __half g_Wph[(size_t)G4 * 1024];       // W_hh: N-perm + k-pack
__device__ __align__(256) __half g_Wo[(size_t)V * 1024];         // W_out: k-pack fp16
__device__ __align__(256) __half g_h0q[(size_t)B * 1024];        // h0 fp16 packed
__device__ __align__(256) __half g_hall[(size_t)T_STEPS * B * 1024]; // all h fp16 packed
__device__ __align__(256) float  g_c[B * H];                     // cell state
__device__ __align__(256) float  g_h[B * H];                     // fp32 h_T (tail only)

__device__ __forceinline__ float sigf(float x) { return 1.0f / (1.0f + __expf(-x)); }

__device__ __forceinline__ uint32_t smem_u32(const void* p) {
    uint32_t a;
    asm("{ .reg .u64 t; cvta.to.shared.u64 t, %1; cvt.u32.u64 %0, t; }" : "=r"(a) : "l"(p));
    return a;
}

// D(f32) = A(16x16 row, fp16) * B(16x8 col, fp16) + D
__device__ __forceinline__ void mma_f16_f32(float* c, uint32_t a0, uint32_t a1,
                                            uint32_t a2, uint32_t a3,
                                            uint32_t b0, uint32_t b1) {
    asm volatile(
        "mma.sync.aligned.m16n8k16.row.col.f32.f16.f16.f32 "
        "{%0,%1,%2,%3}, {%4,%5,%6,%7}, {%8,%9}, {%0,%1,%2,%3};"
        : "+f"(c[0]), "+f"(c[1]), "+f"(c[2]), "+f"(c[3])
        : "r"(a0), "r"(a1), "r"(a2), "r"(a3), "r"(b0), "r"(b1));
}

// packed half-offset of k index u within a row
__device__ __forceinline__ int pack_off(int u) {
    int kg = u >> 4, kl = u & 15, q = kl >> 1, b = kl & 1;
    int t = q & 3, ps = q >> 2;
    return kg * 16 + t * 4 + ps * 2 + b;
}

// ---------------------------------------------------------------------------
__global__ void copy_c0_kernel(const float* __restrict__ c0) {
    int i = blockIdx.x * blockDim.x + threadIdx.x;
    reinterpret_cast<float4*>(g_c)[i] = reinterpret_cast<const float4*>(c0)[i];
}

__global__ void h0_q_kernel(const float* __restrict__ h0) {
    int i = blockIdx.x * blockDim.x + threadIdx.x;   // over B*H
    int m = i >> 10, u = i & 1023;
    g_h0q[(size_t)m * 1024 + pack_off(u)] = __float2half_rn(h0[i]);
}

// W_out[v][k] -> g_Wo packed fp16
__global__ void packWo_kernel(const float* __restrict__ W_out) {
    int i = blockIdx.x * blockDim.x + threadIdx.x;   // over V*H
    int v = i >> 10, k = i & 1023;
    g_Wo[(size_t)v * 1024 + pack_off(k)] = __float2half_rn(W_out[i]);
}

// proj[v][u*4+gate] = b_ih[g]+b_hh[g] + sum_e emb[v][e]*W_ih[g][e]
__global__ void vocab_proj_kernel(const float* __restrict__ emb,
                                  const float* __restrict__ W_ih,
                                  const float* __restrict__ b_ih,
                                  const float* __restrict__ b_hh) {
    __shared__ float es[E];
    int v = blockIdx.x;
    if (threadIdx.x < E) es[threadIdx.x] = emb[v * E + threadIdx.x];
    __syncthreads();
    for (int g = threadIdx.x; g < G4; g += blockDim.x) {
        float s = b_ih[g] + b_hh[g];
        const float* w = W_ih + g * E;
#pragma unroll
        for (int e = 0; e < E; e++) s += es[e] * w[e];
        int gate = g >> 10;
        int u = g & (H - 1);
        g_proj[v * G4 + u * 4 + gate] = s;
    }
}

// W_hh[gate*H+u][k] -> g_Wph with N-perm + k-pack, fp16.
// N-perm: n = 16*(u>>2) + 2*(u&3) + 8*(gate>>1) + (gate&1)
__global__ void permW_hi_kernel(const float* __restrict__ W_hh) {
    int idx = blockIdx.x * blockDim.x + threadIdx.x;  // over G4*H
    int g = idx >> 10;
    int k = idx & (H - 1);
    int gate = g >> 10, u = g & (H - 1);
    int n = ((u >> 2) << 4) + ((u & 3) << 1) + ((gate >> 1) << 3) + (gate & 1);
    g_Wph[(size_t)n * 1024 + pack_off(k)] = __float2half_rn(W_hh[idx]);
}

// ---------------------------------------------------------------------------
// LSTM step: pre = fp16(h) @ fp16(W)^T, f32 accum. Block 128x128, 8 warps
// (2m x 4n), warp tile 64x32, 64 k16 stages, 6-deep cp.async, 2 CTAs/SM.
__global__ __launch_bounds__(256, 2)
void lstm_step_mma(int t, const int* __restrict__ ids_full) {
    extern __shared__ __align__(128) uint8_t smem[];
    const uint32_t sb = smem_u32(smem);

    const int tid = threadIdx.x;
    const int wid = tid >> 5;
    const int lane = tid & 31;
    const int gq = lane >> 2;
    const int tq = lane & 3;
    const int wm = wid >> 2;       // 0..1
    const int wn = wid & 3;        // 0..3
    const int m0 = blockIdx.y * 128;
    const int n0 = blockIdx.x * 128;

    const __half* __restrict__ Asrc =
        (t == 0) ? g_h0q : (g_hall + (size_t)(t - 1) * B * 1024);
    const __half* __restrict__ Bsrc = g_Wph;

    auto load_stage = [&](int s) {
        uint32_t buf = sb + (uint32_t)(s % DST) * STAGE_BYTES;
#pragma unroll
        for (int i = 0; i < 2; i++) {
            int c = tid + (i << 8);
            int isB = c >> 8;
            int cc = c & 255;
            int row = cc >> 1, tt = cc & 1;
            const __half* src = isB
                ? (Bsrc + (size_t)(n0 + row) * 1024 + s * 16 + tt * 8)
                : (Asrc + (size_t)(m0 + row) * 1024 + s * 16 + tt * 8);
            uint32_t dst = buf + (uint32_t)(isB << 12) + (uint32_t)(row * 32 + tt * 16);
            asm volatile("cp.async.cg.shared.global [%0], [%1], 16;"
                         :: "r"(dst), "l"(src));
        }
        asm volatile("cp.async.commit_group;" ::: "memory");
    };

    float accM[4][4][4];
#pragma unroll
    for (int i = 0; i < 4; i++)
#pragma unroll
        for (int j = 0; j < 4; j++)
#pragma unroll
            for (int k = 0; k < 4; k++) accM[i][j][k] = 0.f;

#pragma unroll
    for (int s = 0; s < DST - 1; s++) load_stage(s);

    for (int s = 0; s < 64; ++s) {
        asm volatile("cp.async.wait_group %0;" :: "n"(DST - 2) : "memory");
        __syncthreads();

        const uint8_t* buf = smem + (s % DST) * STAGE_BYTES;

        uint2 Bf[4];
#pragma unroll
        for (int ni = 0; ni < 4; ni++) {
            int row = 32 * wn + 8 * ni + gq;
            Bf[ni] = *reinterpret_cast<const uint2*>(buf + 4096 + row * 32 + tq * 8);
        }
#pragma unroll
        for (int mi = 0; mi < 4; mi++) {
            int rowa = 64 * wm + 16 * mi + gq;
            uint2 A0 = *reinterpret_cast<const uint2*>(buf + rowa * 32 + tq * 8);
            uint2 A1 = *reinterpret_cast<const uint2*>(buf + (rowa + 8) * 32 + tq * 8);
#pragma unroll
            for (int ni = 0; ni < 4; ni++) {
                mma_f16_f32(accM[mi][ni], A0.x, A1.x, A0.y, A1.y, Bf[ni].x, Bf[ni].y);
            }
        }

        if (s + DST - 1 < 64) load_stage(s + DST - 1);
        else asm volatile("cp.async.commit_group;" ::: "memory");
    }

    // ---- fused LSTM epilogue ----
    const int* __restrict__ ids = ids_full + t * B;
    __half* __restrict__ hdst = g_hall + (size_t)t * B * 1024;
    const bool last = (t == T_STEPS - 1);

#pragma unroll
    for (int mi = 0; mi < 4; mi++) {
#pragma unroll
        for (int rsel = 0; rsel < 2; rsel++) {
            int m = m0 + 64 * wm + 16 * mi + 8 * rsel + gq;
            int id = __ldg(&ids[m]);
            const float4* __restrict__ pv =
                reinterpret_cast<const float4*>(g_proj + (size_t)id * G4);
#pragma unroll
            for (int p = 0; p < 2; p++) {
                int u = ((n0 + 32 * wn + 16 * p) >> 2) + tq;
                float4 P = pv[u];
                int ai = 2 * rsel;
                float pre_i = accM[mi][2*p  ][ai  ] + P.x;
                float pre_f = accM[mi][2*p  ][ai+1] + P.y;
                float pre_g = accM[mi][2*p+1][ai  ] + P.z;
                float pre_o = accM[mi][2*p+1][ai+1] + P.w;
                size_t cx = (size_t)m * H + u;
                float c = sigf(pre_f) * g_c[cx] + sigf(pre_i) * tanhf(pre_g);
                g_c[cx] = c;
                float h = sigf(pre_o) * tanhf(c);
                hdst[(size_t)m * 1024 + pack_off(u)] = __float2half_rn(h);
                if (last) g_h[cx] = h;
            }
        }
    }
}

// ---------------------------------------------------------------------------
// out_proj via HMMA: scores[m][v] = h[m] . W_out[v] + b_out[v]
// M=86016, N=96, K=1024. Block 128x96, 8 warps (one 16-row slab each, 12 n-frags).
__global__ __launch_bounds__(256, 2)
void out_proj_mma(const float* __restrict__ b_out, float* __restrict__ scores) {
    extern __shared__ __align__(128) uint8_t smem[];
    const uint32_t sb = smem_u32(smem);

    const int tid = threadIdx.x;
    const int wid = tid >> 5;
    const int lane = tid & 31;
    const int gq = lane >> 2;
    const int tq = lane & 3;
    const int m0 = blockIdx.x * 128;

    auto load_stage = [&](int s) {
        uint32_t buf = sb + (uint32_t)(s % DST) * STAGE_BYTES;
        {   // A: 256 chunks of 16B, 1/thread
            int row = tid >> 1, tt = tid & 1;
            const __half* src = g_hall + (size_t)(m0 + row) * 1024 + s * 16 + tt * 8;
            uint32_t dst = buf + (uint32_t)(row * 32 + tt * 16);
            asm volatile("cp.async.cg.shared.global [%0], [%1], 16;"
                         :: "r"(dst), "l"(src));
        }
        if (tid < 192) {  // B: 96 rows x 2 chunks
            int row = tid >> 1, tt = tid & 1;
            const __half* src = g_Wo + (size_t)row * 1024 + s * 16 + tt * 8;
            uint32_t dst = buf + 4096u + (uint32_t)(row * 32 + tt * 16);
            asm volatile("cp.async.cg.shared.global [%0], [%1], 16;"
                         :: "r"(dst), "l"(src));
        }
        asm volatile("cp.async.commit_group;" ::: "memory");
    };

    float acc[12][4];
#pragma unroll
    for (int i = 0; i < 12; i++)
#pragma unroll
        for (int j = 0; j < 4; j++) acc[i][j] = 0.f;

#pragma unroll
    for (int s = 0; s < DST - 1; s++) load_stage(s);

    for (int s = 0; s < 64; ++s) {
        asm volatile("cp.async.wait_group %0;" :: "n"(DST - 2) : "memory");
        __syncthreads();

        const uint8_t* buf = smem + (s % DST) * STAGE_BYTES;

        int rowa = 16 * wid + gq;
        uint2 A0 = *reinterpret_cast<const uint2*>(buf + rowa * 32 + tq * 8);
        uint2 A1 = *reinterpret_cast<const uint2*>(buf + (rowa + 8) * 32 + tq * 8);
#pragma unroll
        for (int ni = 0; ni < 12; ni++) {
            int row = 8 * ni + gq;
            uint2 Bf = *reinterpret_cast<const uint2*>(buf + 4096 + row * 32 + tq * 8);
            mma_f16_f32(acc[ni], A0.x, A1.x, A0.y, A1.y, Bf.x, Bf.y);
        }

        if (s + DST - 1 < 64) load_stage(s + DST - 1);
        else asm volatile("cp.async.commit_group;" ::: "memory");
    }

#pragma unroll
    for (int rsel = 0; rsel < 2; rsel++) {
        int m = m0 + 16 * wid + 8 * rsel + gq;
#pragma unroll
        for (int ni = 0; ni < 12; ni++) {
            int v = ni * 8 + tq * 2;
            float2 o;
            o.x = acc[ni][2 * rsel]     + __ldg(&b_out[v]);
            o.y = acc[ni][2 * rsel + 1] + __ldg(&b_out[v + 1]);
            *reinterpret_cast<float2*>(scores + (size_t)m * V + v) = o;
        }
    }
}

// ---------------------------------------------------------------------------
__global__ void tail_kernel(float* __restrict__ out) {
    int i = blockIdx.x * blockDim.x + threadIdx.x;
    float4* oh = reinterpret_cast<float4*>(out + (size_t)T_STEPS * B * V);
    float4* oc = oh + (B * H / 4);
    oh[i] = reinterpret_cast<const float4*>(g_h)[i];
    oc[i] = reinterpret_cast<const float4*>(g_c)[i];
}

// ---------------------------------------------------------------------------
extern "C" void kernel_launch(void* const* d_in, const int* in_sizes, int n_in,
                              void* d_out, int out_size) {
    const int*   ids   = (const int*)  d_in[0];
    const float* h0    = (const float*)d_in[1];
    const float* c0    = (const float*)d_in[2];
    const float* emb   = (const float*)d_in[3];
    const float* W_ih  = (const float*)d_in[4];
    const float* W_hh  = (const float*)d_in[5];
    const float* b_ih  = (const float*)d_in[6];
    const float* b_hh  = (const float*)d_in[7];
    const float* W_out = (const float*)d_in[8];
    const float* b_out = (const float*)d_in[9];
    float* out = (float*)d_out;

    cudaFuncSetAttribute(lstm_step_mma, cudaFuncAttributeMaxDynamicSharedMemorySize,
                         SMEM_TOTAL);
    cudaFuncSetAttribute(out_proj_mma, cudaFuncAttributeMaxDynamicSharedMemorySize,
                         SMEM_TOTAL);

    copy_c0_kernel<<<B * H / 4 / 256, 256>>>(c0);
    h0_q_kernel<<<B * H / 256, 256>>>(h0);
    packWo_kernel<<<V * H / 256, 256>>>(W_out);
    vocab_proj_kernel<<<V, 256>>>(emb, W_ih, b_ih, b_hh);
    permW_hi_kernel<<<G4 * H / 256, 256>>>(W_hh);

    dim3 gemm_grid(G4 / 128, B / 128);  // 32 x 32 = 1024 CTAs
    for (int t = 0; t < T_STEPS; ++t) {
        lstm_step_mma<<<gemm_grid, 256, SMEM_TOTAL>>>(t, ids);
    }

    out_proj_mma<<<(T_STEPS * B) / 128, 256, SMEM_TOTAL>>>(b_out, out);
    tail_kernel<<<B * H / 4 / 256, 256>>>(out);
}

// round 11
// speedup vs baseline: 8.1961x; 1.0157x over previous
#include <cuda_runtime.h>
#include <cuda_fp16.h>
#include <math.h>
#include <cstdint>

#define T_STEPS 21
#define B 4096
#define H 1024
#define E 50
#define V 96
#define G4 4096  // 4*H

#define DST 6                 // pipeline stages
#define STAGE_BYTES 8192      // A 4KB + B 4KB per k16 stage
#define SMEM_TOTAL (DST * STAGE_BYTES)

// ---------------- device globals (no allocs allowed) ----------------
// Packed fp16 row layout (1024 k): half offset = row*1024 + pack_off(k)
__device__ __align__(256) float  g_proj[V * G4];                 // [v][u*4+gate]
__device__ __align__(256) __half g_Wph[(size_t)G4 * 1024];       // W_hh: N-perm + k-pack
__device__ __align__(256) __half g_Wo[(size_t)V * 1024];         // W_out: k-pack fp16
__device__ __align__(256) __half g_h0q[(size_t)B * 1024];        // h0 fp16 packed
__device__ __align__(256) __half g_hall[(size_t)T_STEPS * B * 1024]; // all h fp16 packed
__device__ __align__(256) float  g_c[B * H];                     // cell state

__device__ __forceinline__ float sigf(float x) { return 1.0f / (1.0f + __expf(-x)); }
__device__ __forceinline__ float tanha(float x) {
    float y;
    asm("tanh.approx.f32 %0, %1;" : "=f"(y) : "f"(x));
    return y;
}

__device__ __forceinline__ uint32_t smem_u32(const void* p) {
    uint32_t a;
    asm("{ .reg .u64 t; cvta.to.shared.u64 t, %1; cvt.u32.u64 %0, t; }" : "=r"(a) : "l"(p));
    return a;
}

// D(f32) = A(16x16 row, fp16) * B(16x8 col, fp16) + D
__device__ __forceinline__ void mma_f16_f32(float* c, uint32_t a0, uint32_t a1,
                                            uint32_t a2, uint32_t a3,
                                            uint32_t b0, uint32_t b1) {
    asm volatile(
        "mma.sync.aligned.m16n8k16.row.col.f32.f16.f16.f32 "
        "{%0,%1,%2,%3}, {%4,%5,%6,%7}, {%8,%9}, {%0,%1,%2,%3};"
        : "+f"(c[0]), "+f"(c[1]), "+f"(c[2]), "+f"(c[3])
        : "r"(a0), "r"(a1), "r"(a2), "r"(a3), "r"(b0), "r"(b1));
}

// packed half-offset of k index u within a row
__device__ __forceinline__ int pack_off(int u) {
    int kg = u >> 4, kl = u & 15, q = kl >> 1, b = kl & 1;
    int t = q & 3, ps = q >> 2;
    return kg * 16 + t * 4 + ps * 2 + b;
}

// ---------------------------------------------------------------------------
// merged init: g_c = c0 (layout-preserving), g_h0q = fp16 pack of h0
__global__ void init_state_kernel(const float* __restrict__ h0,
                                  const float* __restrict__ c0) {
    int i = blockIdx.x * blockDim.x + threadIdx.x;   // over B*H
    int m = i >> 10, u = i & 1023;
    g_c[i] = c0[i];
    g_h0q[(size_t)m * 1024 + pack_off(u)] = __float2half_rn(h0[i]);
}

// W_out[v][k] -> g_Wo packed fp16
__global__ void packWo_kernel(const float* __restrict__ W_out) {
    int i = blockIdx.x * blockDim.x + threadIdx.x;   // over V*H
    int v = i >> 10, k = i & 1023;
    g_Wo[(size_t)v * 1024 + pack_off(k)] = __float2half_rn(W_out[i]);
}

// proj[v][u*4+gate] = b_ih[g]+b_hh[g] + sum_e emb[v][e]*W_ih[g][e]
// grid (V, 8): block y covers 512 gates
__global__ void vocab_proj_kernel(const float* __restrict__ emb,
                                  const float* __restrict__ W_ih,
                                  const float* __restrict__ b_ih,
                                  const float* __restrict__ b_hh) {
    __shared__ float es[E];
    int v = blockIdx.x;
    if (threadIdx.x < E) es[threadIdx.x] = emb[v * E + threadIdx.x];
    __syncthreads();
    int g0 = blockIdx.y * 512;
    for (int g = g0 + threadIdx.x; g < g0 + 512; g += blockDim.x) {
        float s = b_ih[g] + b_hh[g];
        const float* w = W_ih + g * E;
#pragma unroll
        for (int e = 0; e < E; e++) s += es[e] * w[e];
        int gate = g >> 10;
        int u = g & (H - 1);
        g_proj[v * G4 + u * 4 + gate] = s;
    }
}

// W_hh[gate*H+u][k] -> g_Wph with N-perm + k-pack, fp16.
// N-perm: n = 16*(u>>2) + 2*(u&3) + 8*(gate>>1) + (gate&1)
__global__ void permW_hi_kernel(const float* __restrict__ W_hh) {
    int idx = blockIdx.x * blockDim.x + threadIdx.x;  // over G4*H
    int g = idx >> 10;
    int k = idx & (H - 1);
    int gate = g >> 10, u = g & (H - 1);
    int n = ((u >> 2) << 4) + ((u & 3) << 1) + ((gate >> 1) << 3) + (gate & 1);
    g_Wph[(size_t)n * 1024 + pack_off(k)] = __float2half_rn(W_hh[idx]);
}

// ---------------------------------------------------------------------------
// LSTM step: pre = fp16(h) @ fp16(W)^T, f32 accum. Block 128x128, 8 warps
// (2m x 4n), warp tile 64x32, 64 k16 stages, 6-deep cp.async, 2 CTAs/SM.
// Last step writes h_T/c_T directly into the output tail.
__global__ __launch_bounds__(256, 2)
void lstm_step_mma(int t, const int* __restrict__ ids_full, float* __restrict__ out) {
    extern __shared__ __align__(128) uint8_t smem[];
    const uint32_t sb = smem_u32(smem);

    const int tid = threadIdx.x;
    const int wid = tid >> 5;
    const int lane = tid & 31;
    const int gq = lane >> 2;
    const int tq = lane & 3;
    const int wm = wid >> 2;       // 0..1
    const int wn = wid & 3;        // 0..3
    const int m0 = blockIdx.y * 128;
    const int n0 = blockIdx.x * 128;

    const __half* __restrict__ Asrc =
        (t == 0) ? g_h0q : (g_hall + (size_t)(t - 1) * B * 1024);
    const __half* __restrict__ Bsrc = g_Wph;

    auto load_stage = [&](int s) {
        uint32_t buf = sb + (uint32_t)(s % DST) * STAGE_BYTES;
#pragma unroll
        for (int i = 0; i < 2; i++) {
            int c = tid + (i << 8);
            int isB = c >> 8;
            int cc = c & 255;
            int row = cc >> 1, tt = cc & 1;
            const __half* src = isB
                ? (Bsrc + (size_t)(n0 + row) * 1024 + s * 16 + tt * 8)
                : (Asrc + (size_t)(m0 + row) * 1024 + s * 16 + tt * 8);
            uint32_t dst = buf + (uint32_t)(isB << 12) + (uint32_t)(row * 32 + tt * 16);
            asm volatile("cp.async.cg.shared.global [%0], [%1], 16;"
                         :: "r"(dst), "l"(src));
        }
        asm volatile("cp.async.commit_group;" ::: "memory");
    };

    float accM[4][4][4];
#pragma unroll
    for (int i = 0; i < 4; i++)
#pragma unroll
        for (int j = 0; j < 4; j++)
#pragma unroll
            for (int k = 0; k < 4; k++) accM[i][j][k] = 0.f;

#pragma unroll
    for (int s = 0; s < DST - 1; s++) load_stage(s);

    for (int s = 0; s < 64; ++s) {
        asm volatile("cp.async.wait_group %0;" :: "n"(DST - 2) : "memory");
        __syncthreads();

        const uint8_t* buf = smem + (s % DST) * STAGE_BYTES;

        uint2 Bf[4];
#pragma unroll
        for (int ni = 0; ni < 4; ni++) {
            int row = 32 * wn + 8 * ni + gq;
            Bf[ni] = *reinterpret_cast<const uint2*>(buf + 4096 + row * 32 + tq * 8);
        }
#pragma unroll
        for (int mi = 0; mi < 4; mi++) {
            int rowa = 64 * wm + 16 * mi + gq;
            uint2 A0 = *reinterpret_cast<const uint2*>(buf + rowa * 32 + tq * 8);
            uint2 A1 = *reinterpret_cast<const uint2*>(buf + (rowa + 8) * 32 + tq * 8);
#pragma unroll
            for (int ni = 0; ni < 4; ni++) {
                mma_f16_f32(accM[mi][ni], A0.x, A1.x, A0.y, A1.y, Bf[ni].x, Bf[ni].y);
            }
        }

        if (s + DST - 1 < 64) load_stage(s + DST - 1);
        else asm volatile("cp.async.commit_group;" ::: "memory");
    }

    // ---- fused LSTM epilogue ----
    const int* __restrict__ ids = ids_full + t * B;
    __half* __restrict__ hdst = g_hall + (size_t)t * B * 1024;
    const bool last = (t == T_STEPS - 1);
    float* __restrict__ out_h = out + (size_t)T_STEPS * B * V;
    float* __restrict__ out_c = out_h + (size_t)B * H;

#pragma unroll
    for (int mi = 0; mi < 4; mi++) {
#pragma unroll
        for (int rsel = 0; rsel < 2; rsel++) {
            int m = m0 + 64 * wm + 16 * mi + 8 * rsel + gq;
            int id = __ldg(&ids[m]);
            const float4* __restrict__ pv =
                reinterpret_cast<const float4*>(g_proj + (size_t)id * G4);
#pragma unroll
            for (int p = 0; p < 2; p++) {
                int u = ((n0 + 32 * wn + 16 * p) >> 2) + tq;
                float4 P = pv[u];
                int ai = 2 * rsel;
                float pre_i = accM[mi][2*p  ][ai  ] + P.x;
                float pre_f = accM[mi][2*p  ][ai+1] + P.y;
                float pre_g = accM[mi][2*p+1][ai  ] + P.z;
                float pre_o = accM[mi][2*p+1][ai+1] + P.w;
                size_t cx = (size_t)m * H + u;
                float c = sigf(pre_f) * g_c[cx] + sigf(pre_i) * tanha(pre_g);
                g_c[cx] = c;
                float h = sigf(pre_o) * tanha(c);
                hdst[(size_t)m * 1024 + pack_off(u)] = __float2half_rn(h);
                if (last) { out_h[cx] = h; out_c[cx] = c; }
            }
        }
    }
}

// ---------------------------------------------------------------------------
// out_proj via HMMA: scores[m][v] = h[m] . W_out[v] + b_out[v]
// M=86016, N=96, K=1024. Block 128x96, 8 warps (one 16-row slab each, 12 n-frags).
__global__ __launch_bounds__(256, 2)
void out_proj_mma(const float* __restrict__ b_out, float* __restrict__ scores) {
    extern __shared__ __align__(128) uint8_t smem[];
    const uint32_t sb = smem_u32(smem);

    const int tid = threadIdx.x;
    const int wid = tid >> 5;
    const int lane = tid & 31;
    const int gq = lane >> 2;
    const int tq = lane & 3;
    const int m0 = blockIdx.x * 128;

    auto load_stage = [&](int s) {
        uint32_t buf = sb + (uint32_t)(s % DST) * STAGE_BYTES;
        {   // A: 256 chunks of 16B, 1/thread
            int row = tid >> 1, tt = tid & 1;
            const __half* src = g_hall + (size_t)(m0 + row) * 1024 + s * 16 + tt * 8;
            uint32_t dst = buf + (uint32_t)(row * 32 + tt * 16);
            asm volatile("cp.async.cg.shared.global [%0], [%1], 16;"
                         :: "r"(dst), "l"(src));
        }
        if (tid < 192) {  // B: 96 rows x 2 chunks
            int row = tid >> 1, tt = tid & 1;
            const __half* src = g_Wo + (size_t)row * 1024 + s * 16 + tt * 8;
            uint32_t dst = buf + 4096u + (uint32_t)(row * 32 + tt * 16);
            asm volatile("cp.async.cg.shared.global [%0], [%1], 16;"
                         :: "r"(dst), "l"(src));
        }
        asm volatile("cp.async.commit_group;" ::: "memory");
    };

    float acc[12][4];
#pragma unroll
    for (int i = 0; i < 12; i++)
#pragma unroll
        for (int j = 0; j < 4; j++) acc[i][j] = 0.f;

#pragma unroll
    for (int s = 0; s < DST - 1; s++) load_stage(s);

    for (int s = 0; s < 64; ++s) {
        asm volatile("cp.async.wait_group %0;" :: "n"(DST - 2) : "memory");
        __syncthreads();

        const uint8_t* buf = smem + (s % DST) * STAGE_BYTES;

        int rowa = 16 * wid + gq;
        uint2 A0 = *reinterpret_cast<const uint2*>(buf + rowa * 32 + tq * 8);
        uint2 A1 = *reinterpret_cast<const uint2*>(buf + (rowa + 8) * 32 + tq * 8);
#pragma unroll
        for (int ni = 0; ni < 12; ni++) {
            int row = 8 * ni + gq;
            uint2 Bf = *reinterpret_cast<const uint2*>(buf + 4096 + row * 32 + tq * 8);
            mma_f16_f32(acc[ni], A0.x, A1.x, A0.y, A1.y, Bf.x, Bf.y);
        }

        if (s + DST - 1 < 64) load_stage(s + DST - 1);
        else asm volatile("cp.async.commit_group;" ::: "memory");
    }

#pragma unroll
    for (int rsel = 0; rsel < 2; rsel++) {
        int m = m0 + 16 * wid + 8 * rsel + gq;
#pragma unroll
        for (int ni = 0; ni < 12; ni++) {
            int v = ni * 8 + tq * 2;
            float2 o;
            o.x = acc[ni][2 * rsel]     + __ldg(&b_out[v]);
            o.y = acc[ni][2 * rsel + 1] + __ldg(&b_out[v + 1]);
            *reinterpret_cast<float2*>(scores + (size_t)m * V + v) = o;
        }
    }
}

// ---------------------------------------------------------------------------
extern "C" void kernel_launch(void* const* d_in, const int* in_sizes, int n_in,
                              void* d_out, int out_size) {
    const int*   ids   = (const int*)  d_in[0];
    const float* h0    = (const float*)d_in[1];
    const float* c0    = (const float*)d_in[2];
    const float* emb   = (const float*)d_in[3];
    const float* W_ih  = (const float*)d_in[4];
    const float* W_hh  = (const float*)d_in[5];
    const float* b_ih  = (const float*)d_in[6];
    const float* b_hh  = (const float*)d_in[7];
    const float* W_out = (const float*)d_in[8];
    const float* b_out = (const float*)d_in[9];
    float* out = (float*)d_out;

    cudaFuncSetAttribute(lstm_step_mma, cudaFuncAttributeMaxDynamicSharedMemorySize,
                         SMEM_TOTAL);
    cudaFuncSetAttribute(out_proj_mma, cudaFuncAttributeMaxDynamicSharedMemorySize,
                         SMEM_TOTAL);

    init_state_kernel<<<B * H / 256, 256>>>(h0, c0);
    packWo_kernel<<<V * H / 256, 256>>>(W_out);
    vocab_proj_kernel<<<dim3(V, 8), 256>>>(emb, W_ih, b_ih, b_hh);
    permW_hi_kernel<<<G4 * H / 256, 256>>>(W_hh);

    dim3 gemm_grid(G4 / 128, B / 128);  // 32 x 32 = 1024 CTAs
    for (int t = 0; t < T_STEPS; ++t) {
        lstm_step_mma<<<gemm_grid, 256, SMEM_TOTAL>>>(t, ids, out);
    }

    out_proj_mma<<<(T_STEPS * B) / 128, 256, SMEM_TOTAL>>>(b_out, out);
}

// round 12
// speedup vs baseline: 8.3748x; 1.0218x over previous
#include <cuda_runtime.h>
#include <cuda_fp16.h>
#include <math.h>
#include <cstdint>

#define T_STEPS 21
#define B 4096
#define H 1024
#define E 50
#define V 96
#define G4 4096  // 4*H

#define DST 6                 // pipeline stages
#define STAGE_BYTES 8192      // A 4KB + B 4KB per k16 stage
#define SMEM_TOTAL (DST * STAGE_BYTES)

// ---------------- device globals (no allocs allowed) ----------------
// Packed fp16 row layout (1024 k): half offset = row*1024 + pack_off(k)
__device__ __align__(256) float  g_proj[V * G4];                 // [v][u*4+gate]
__device__ __align__(256) __half g_Wph[(size_t)G4 * 1024];       // W_hh: N-perm + k-pack
__device__ __align__(256) __half g_Wo[(size_t)V * 1024];         // W_out: k-pack fp16
__device__ __align__(256) __half g_h0q[(size_t)B * 1024];        // h0 fp16 packed
__device__ __align__(256) __half g_hall[(size_t)T_STEPS * B * 1024]; // all h fp16 packed
__device__ __align__(256) float  g_c[B * H];                     // cell state

__device__ __forceinline__ float sigf(float x) { return 1.0f / (1.0f + __expf(-x)); }
__device__ __forceinline__ float tanha(float x) {
    float y;
    asm("tanh.approx.f32 %0, %1;" : "=f"(y) : "f"(x));
    return y;
}

__device__ __forceinline__ uint32_t smem_u32(const void* p) {
    uint32_t a;
    asm("{ .reg .u64 t; cvta.to.shared.u64 t, %1; cvt.u32.u64 %0, t; }" : "=r"(a) : "l"(p));
    return a;
}

// D(f32) = A(16x16 row, fp16) * B(16x8 col, fp16) + D
__device__ __forceinline__ void mma_f16_f32(float* c, uint32_t a0, uint32_t a1,
                                            uint32_t a2, uint32_t a3,
                                            uint32_t b0, uint32_t b1) {
    asm volatile(
        "mma.sync.aligned.m16n8k16.row.col.f32.f16.f16.f32 "
        "{%0,%1,%2,%3}, {%4,%5,%6,%7}, {%8,%9}, {%0,%1,%2,%3};"
        : "+f"(c[0]), "+f"(c[1]), "+f"(c[2]), "+f"(c[3])
        : "r"(a0), "r"(a1), "r"(a2), "r"(a3), "r"(b0), "r"(b1));
}

// packed half-offset of k index u within a row
__device__ __forceinline__ int pack_off(int u) {
    int kg = u >> 4, kl = u & 15, q = kl >> 1, b = kl & 1;
    int t = q & 3, ps = q >> 2;
    return kg * 16 + t * 4 + ps * 2 + b;
}

// ---------------------------------------------------------------------------
// merged init: g_c = c0, g_h0q = fp16 pack of h0
__global__ void init_state_kernel(const float* __restrict__ h0,
                                  const float* __restrict__ c0) {
    int i = blockIdx.x * blockDim.x + threadIdx.x;   // over B*H
    int m = i >> 10, u = i & 1023;
    g_c[i] = c0[i];
    g_h0q[(size_t)m * 1024 + pack_off(u)] = __float2half_rn(h0[i]);
}

// W_out[v][k] -> g_Wo packed fp16
__global__ void packWo_kernel(const float* __restrict__ W_out) {
    int i = blockIdx.x * blockDim.x + threadIdx.x;   // over V*H
    int v = i >> 10, k = i & 1023;
    g_Wo[(size_t)v * 1024 + pack_off(k)] = __float2half_rn(W_out[i]);
}

// proj[v][u*4+gate] = b_ih[g]+b_hh[g] + sum_e emb[v][e]*W_ih[g][e]
// grid (V, 8)
__global__ void vocab_proj_kernel(const float* __restrict__ emb,
                                  const float* __restrict__ W_ih,
                                  const float* __restrict__ b_ih,
                                  const float* __restrict__ b_hh) {
    __shared__ float es[E];
    int v = blockIdx.x;
    if (threadIdx.x < E) es[threadIdx.x] = emb[v * E + threadIdx.x];
    __syncthreads();
    int g0 = blockIdx.y * 512;
    for (int g = g0 + threadIdx.x; g < g0 + 512; g += blockDim.x) {
        float s = b_ih[g] + b_hh[g];
        const float* w = W_ih + g * E;
#pragma unroll
        for (int e = 0; e < E; e++) s += es[e] * w[e];
        int gate = g >> 10;
        int u = g & (H - 1);
        g_proj[v * G4 + u * 4 + gate] = s;
    }
}

// W_hh -> g_Wph, vectorized: each thread emits one 8B packed chunk (4 k's).
// chunk c of row n: kg=c>>2, t=c&3; k = {16kg+2t, +1, +8, +9}
// inverse N-perm: gate = ((n>>3)&1)*2 + (n&1); u = (n>>4)*4 + ((n>>1)&3)
__global__ void permW_hi_kernel(const float* __restrict__ W_hh) {
    int i = blockIdx.x * blockDim.x + threadIdx.x;   // over G4*256 chunks
    int n = i >> 8, c = i & 255;
    int kg = c >> 2, t = c & 3;
    int gate = (((n >> 3) & 1) << 1) | (n & 1);
    int u = ((n >> 4) << 2) | ((n >> 1) & 3);
    const float* src = W_hh + (size_t)(gate * H + u) * H + kg * 16 + 2 * t;
    float2 p0 = *reinterpret_cast<const float2*>(src);      // k, k+1
    float2 p1 = *reinterpret_cast<const float2*>(src + 8);  // k+8, k+9
    __half2 h0 = __floats2half2_rn(p0.x, p0.y);
    __half2 h1 = __floats2half2_rn(p1.x, p1.y);
    uint2 pk = make_uint2(*reinterpret_cast<uint32_t*>(&h0),
                          *reinterpret_cast<uint32_t*>(&h1));
    *reinterpret_cast<uint2*>(g_Wph + (size_t)n * 1024 + c * 4) = pk;
}

// ---------------------------------------------------------------------------
// LSTM step: pre = fp16(h) @ fp16(W)^T, f32 accum. Block 128x128, 8 warps
// (2m x 4n), warp tile 64x32, 64 k16 stages, 6-deep cp.async, 2 CTAs/SM.
__global__ __launch_bounds__(256, 2)
void lstm_step_mma(int t, const int* __restrict__ ids_full, float* __restrict__ out) {
    extern __shared__ __align__(128) uint8_t smem[];
    const uint32_t sb = smem_u32(smem);

    const int tid = threadIdx.x;
    const int wid = tid >> 5;
    const int lane = tid & 31;
    const int gq = lane >> 2;
    const int tq = lane & 3;
    const int wm = wid >> 2;       // 0..1
    const int wn = wid & 3;        // 0..3
    const int m0 = blockIdx.y * 128;
    const int n0 = blockIdx.x * 128;

    const __half* __restrict__ Asrc =
        (t == 0) ? g_h0q : (g_hall + (size_t)(t - 1) * B * 1024);
    const __half* __restrict__ Bsrc = g_Wph;

    auto load_stage = [&](int s) {
        uint32_t buf = sb + (uint32_t)(s % DST) * STAGE_BYTES;
#pragma unroll
        for (int i = 0; i < 2; i++) {
            int c = tid + (i << 8);
            int isB = c >> 8;
            int cc = c & 255;
            int row = cc >> 1, tt = cc & 1;
            const __half* src = isB
                ? (Bsrc + (size_t)(n0 + row) * 1024 + s * 16 + tt * 8)
                : (Asrc + (size_t)(m0 + row) * 1024 + s * 16 + tt * 8);
            uint32_t dst = buf + (uint32_t)(isB << 12) + (uint32_t)(row * 32 + tt * 16);
            asm volatile("cp.async.cg.shared.global [%0], [%1], 16;"
                         :: "r"(dst), "l"(src));
        }
        asm volatile("cp.async.commit_group;" ::: "memory");
    };

    float accM[4][4][4];
#pragma unroll
    for (int i = 0; i < 4; i++)
#pragma unroll
        for (int j = 0; j < 4; j++)
#pragma unroll
            for (int k = 0; k < 4; k++) accM[i][j][k] = 0.f;

#pragma unroll
    for (int s = 0; s < DST - 1; s++) load_stage(s);

    for (int s = 0; s < 64; ++s) {
        asm volatile("cp.async.wait_group %0;" :: "n"(DST - 2) : "memory");
        __syncthreads();

        const uint8_t* buf = smem + (s % DST) * STAGE_BYTES;

        uint2 Bf[4];
#pragma unroll
        for (int ni = 0; ni < 4; ni++) {
            int row = 32 * wn + 8 * ni + gq;
            Bf[ni] = *reinterpret_cast<const uint2*>(buf + 4096 + row * 32 + tq * 8);
        }
#pragma unroll
        for (int mi = 0; mi < 4; mi++) {
            int rowa = 64 * wm + 16 * mi + gq;
            uint2 A0 = *reinterpret_cast<const uint2*>(buf + rowa * 32 + tq * 8);
            uint2 A1 = *reinterpret_cast<const uint2*>(buf + (rowa + 8) * 32 + tq * 8);
#pragma unroll
            for (int ni = 0; ni < 4; ni++) {
                mma_f16_f32(accM[mi][ni], A0.x, A1.x, A0.y, A1.y, Bf[ni].x, Bf[ni].y);
            }
        }

        if (s + DST - 1 < 64) load_stage(s + DST - 1);
        else asm volatile("cp.async.commit_group;" ::: "memory");
    }

    // ---- fused LSTM epilogue ----
    const int* __restrict__ ids = ids_full + t * B;
    __half* __restrict__ hdst = g_hall + (size_t)t * B * 1024;
    const bool last = (t == T_STEPS - 1);
    float* __restrict__ out_h = out + (size_t)T_STEPS * B * V;
    float* __restrict__ out_c = out_h + (size_t)B * H;

#pragma unroll
    for (int mi = 0; mi < 4; mi++) {
#pragma unroll
        for (int rsel = 0; rsel < 2; rsel++) {
            int m = m0 + 64 * wm + 16 * mi + 8 * rsel + gq;
            int id = __ldg(&ids[m]);
            const float4* __restrict__ pv =
                reinterpret_cast<const float4*>(g_proj + (size_t)id * G4);
#pragma unroll
            for (int p = 0; p < 2; p++) {
                int u = ((n0 + 32 * wn + 16 * p) >> 2) + tq;
                float4 P = pv[u];
                int ai = 2 * rsel;
                float pre_i = accM[mi][2*p  ][ai  ] + P.x;
                float pre_f = accM[mi][2*p  ][ai+1] + P.y;
                float pre_g = accM[mi][2*p+1][ai  ] + P.z;
                float pre_o = accM[mi][2*p+1][ai+1] + P.w;
                size_t cx = (size_t)m * H + u;
                float c = sigf(pre_f) * g_c[cx] + sigf(pre_i) * tanha(pre_g);
                g_c[cx] = c;
                float h = sigf(pre_o) * tanha(c);
                hdst[(size_t)m * 1024 + pack_off(u)] = __float2half_rn(h);
                if (last) { out_h[cx] = h; out_c[cx] = c; }
            }
        }
    }
}

// ---------------------------------------------------------------------------
// out_proj slice via HMMA for one timestep's 4096 rows (m_base = t*B).
// Block 128x96, 8 warps (16-row slab each, 12 n-frags). Grid 32 CTAs.
__global__ __launch_bounds__(256, 2)
void out_proj_mma(int m_base, const float* __restrict__ b_out,
                  float* __restrict__ scores) {
    extern __shared__ __align__(128) uint8_t smem[];
    const uint32_t sb = smem_u32(smem);

    const int tid = threadIdx.x;
    const int wid = tid >> 5;
    const int lane = tid & 31;
    const int gq = lane >> 2;
    const int tq = lane & 3;
    const int m0 = m_base + blockIdx.x * 128;

    auto load_stage = [&](int s) {
        uint32_t buf = sb + (uint32_t)(s % DST) * STAGE_BYTES;
        {   // A: 256 chunks of 16B, 1/thread
            int row = tid >> 1, tt = tid & 1;
            const __half* src = g_hall + (size_t)(m0 + row) * 1024 + s * 16 + tt * 8;
            uint32_t dst = buf + (uint32_t)(row * 32 + tt * 16);
            asm volatile("cp.async.cg.shared.global [%0], [%1], 16;"
                         :: "r"(dst), "l"(src));
        }
        if (tid < 192) {  // B: 96 rows x 2 chunks
            int row = tid >> 1, tt = tid & 1;
            const __half* src = g_Wo + (size_t)row * 1024 + s * 16 + tt * 8;
            uint32_t dst = buf + 4096u + (uint32_t)(row * 32 + tt * 16);
            asm volatile("cp.async.cg.shared.global [%0], [%1], 16;"
                         :: "r"(dst), "l"(src));
        }
        asm volatile("cp.async.commit_group;" ::: "memory");
    };

    float acc[12][4];
#pragma unroll
    for (int i = 0; i < 12; i++)
#pragma unroll
        for (int j = 0; j < 4; j++) acc[i][j] = 0.f;

#pragma unroll
    for (int s = 0; s < DST - 1; s++) load_stage(s);

    for (int s = 0; s < 64; ++s) {
        asm volatile("cp.async.wait_group %0;" :: "n"(DST - 2) : "memory");
        __syncthreads();

        const uint8_t* buf = smem + (s % DST) * STAGE_BYTES;

        int rowa = 16 * wid + gq;
        uint2 A0 = *reinterpret_cast<const uint2*>(buf + rowa * 32 + tq * 8);
        uint2 A1 = *reinterpret_cast<const uint2*>(buf + (rowa + 8) * 32 + tq * 8);
#pragma unroll
        for (int ni = 0; ni < 12; ni++) {
            int row = 8 * ni + gq;
            uint2 Bf = *reinterpret_cast<const uint2*>(buf + 4096 + row * 32 + tq * 8);
            mma_f16_f32(acc[ni], A0.x, A1.x, A0.y, A1.y, Bf.x, Bf.y);
        }

        if (s + DST - 1 < 64) load_stage(s + DST - 1);
        else asm volatile("cp.async.commit_group;" ::: "memory");
    }

#pragma unroll
    for (int rsel = 0; rsel < 2; rsel++) {
        int m = m0 + 16 * wid + 8 * rsel + gq;
#pragma unroll
        for (int ni = 0; ni < 12; ni++) {
            int v = ni * 8 + tq * 2;
            float2 o;
            o.x = acc[ni][2 * rsel]     + __ldg(&b_out[v]);
            o.y = acc[ni][2 * rsel + 1] + __ldg(&b_out[v + 1]);
            *reinterpret_cast<float2*>(scores + (size_t)m * V + v) = o;
        }
    }
}

// ---------------------------------------------------------------------------
extern "C" void kernel_launch(void* const* d_in, const int* in_sizes, int n_in,
                              void* d_out, int out_size) {
    const int*   ids   = (const int*)  d_in[0];
    const float* h0    = (const float*)d_in[1];
    const float* c0    = (const float*)d_in[2];
    const float* emb   = (const float*)d_in[3];
    const float* W_ih  = (const float*)d_in[4];
    const float* W_hh  = (const float*)d_in[5];
    const float* b_ih  = (const float*)d_in[6];
    const float* b_hh  = (const float*)d_in[7];
    const float* W_out = (const float*)d_in[8];
    const float* b_out = (const float*)d_in[9];
    float* out = (float*)d_out;

    // lazy one-time host-side resources (no device memory involved)
    static cudaStream_t s2 = nullptr;
    static cudaEvent_t evStep[T_STEPS], evJoin;
    if (!s2) {
        cudaStreamCreateWithFlags(&s2, cudaStreamNonBlocking);
        for (int t = 0; t < T_STEPS; ++t)
            cudaEventCreateWithFlags(&evStep[t], cudaEventDisableTiming);
        cudaEventCreateWithFlags(&evJoin, cudaEventDisableTiming);
        cudaFuncSetAttribute(lstm_step_mma, cudaFuncAttributeMaxDynamicSharedMemorySize,
                             SMEM_TOTAL);
        cudaFuncSetAttribute(out_proj_mma, cudaFuncAttributeMaxDynamicSharedMemorySize,
                             SMEM_TOTAL);
    }

    init_state_kernel<<<B * H / 256, 256>>>(h0, c0);
    packWo_kernel<<<V * H / 256, 256>>>(W_out);
    vocab_proj_kernel<<<dim3(V, 8), 256>>>(emb, W_ih, b_ih, b_hh);
    permW_hi_kernel<<<G4 * 256 / 256, 256>>>(W_hh);

    dim3 gemm_grid(G4 / 128, B / 128);  // 32 x 32 = 1024 CTAs
    for (int t = 0; t < T_STEPS; ++t) {
        lstm_step_mma<<<gemm_grid, 256, SMEM_TOTAL>>>(t, ids, out);
        // fork: out_proj slice for step t overlaps with step t+1
        cudaEventRecord(evStep[t], 0);
        cudaStreamWaitEvent(s2, evStep[t], 0);
        out_proj_mma<<<B / 128, 256, SMEM_TOTAL, s2>>>(t * B, b_out, out);
    }
    // join side stream back into the captured (default) stream
    cudaEventRecord(evJoin, s2);
    cudaStreamWaitEvent(0, evJoin, 0);
}

// round 15
// speedup vs baseline: 8.5775x; 1.0242x over previous
#include <cuda_runtime.h>
#include <cuda_fp16.h>
#include <math.h>
#include <cstdint>

#define T_STEPS 21
#define B 4096
#define H 1024
#define E 50
#define V 96
#define G4 4096  // 4*H

#define DST 6                 // pipeline stages
#define STAGE_BYTES 8192      // A 4KB + B 4KB per k16 stage
#define SMEM_TOTAL (DST * STAGE_BYTES)

// ---------------- device globals (no allocs allowed) ----------------
// Packed fp16 row layout (1024 k): half offset = row*1024 + pack_off(k)
__device__ __align__(256) float  g_proj[V * G4];                 // [v][u*4+gate]
__device__ __align__(256) __half g_Wph[(size_t)G4 * 1024];       // W_hh: N-perm + k-pack
__device__ __align__(256) __half g_Wo[(size_t)V * 1024];         // W_out: k-pack fp16
__device__ __align__(256) __half g_h0q[(size_t)B * 1024];        // h0 fp16 packed
__device__ __align__(256) __half g_hall[(size_t)T_STEPS * B * 1024]; // all h fp16 packed
__device__ __align__(256) float  g_c[B * H];                     // cell state

__device__ __forceinline__ float tanha(float x) {
    float y;
    asm("tanh.approx.f32 %0, %1;" : "=f"(y) : "f"(x));
    return y;
}
// sigmoid via MUFU.TANH: 1 MUFU instead of 2 (EX2+RCP)
__device__ __forceinline__ float sigf(float x) {
    return fmaf(0.5f, tanha(0.5f * x), 0.5f);
}

__device__ __forceinline__ uint32_t smem_u32(const void* p) {
    uint32_t a;
    asm("{ .reg .u64 t; cvta.to.shared.u64 t, %1; cvt.u32.u64 %0, t; }" : "=r"(a) : "l"(p));
    return a;
}

// D(f32) = A(16x16 row, fp16) * B(16x8 col, fp16) + D
__device__ __forceinline__ void mma_f16_f32(float* c, uint32_t a0, uint32_t a1,
                                            uint32_t a2, uint32_t a3,
                                            uint32_t b0, uint32_t b1) {
    asm volatile(
        "mma.sync.aligned.m16n8k16.row.col.f32.f16.f16.f32 "
        "{%0,%1,%2,%3}, {%4,%5,%6,%7}, {%8,%9}, {%0,%1,%2,%3};"
        : "+f"(c[0]), "+f"(c[1]), "+f"(c[2]), "+f"(c[3])
        : "r"(a0), "r"(a1), "r"(a2), "r"(a3), "r"(b0), "r"(b1));
}

// packed half-offset of k index u within a row
__device__ __forceinline__ int pack_off(int u) {
    int kg = u >> 4, kl = u & 15, q = kl >> 1, b = kl & 1;
    int t = q & 3, ps = q >> 2;
    return kg * 16 + t * 4 + ps * 2 + b;
}

// ---------------------------------------------------------------------------
// merged init: g_c = c0, g_h0q = fp16 pack of h0
__global__ void init_state_kernel(const float* __restrict__ h0,
                                  const float* __restrict__ c0) {
    int i = blockIdx.x * blockDim.x + threadIdx.x;   // over B*H
    int m = i >> 10, u = i & 1023;
    g_c[i] = c0[i];
    g_h0q[(size_t)m * 1024 + pack_off(u)] = __float2half_rn(h0[i]);
}

// W_out[v][k] -> g_Wo packed fp16
__global__ void packWo_kernel(const float* __restrict__ W_out) {
    int i = blockIdx.x * blockDim.x + threadIdx.x;   // over V*H
    int v = i >> 10, k = i & 1023;
    g_Wo[(size_t)v * 1024 + pack_off(k)] = __float2half_rn(W_out[i]);
}

// proj[v][u*4+gate] = b_ih[g]+b_hh[g] + sum_e emb[v][e]*W_ih[g][e]
// grid (V, 8)
__global__ void vocab_proj_kernel(const float* __restrict__ emb,
                                  const float* __restrict__ W_ih,
                                  const float* __restrict__ b_ih,
                                  const float* __restrict__ b_hh) {
    __shared__ float es[E];
    int v = blockIdx.x;
    if (threadIdx.x < E) es[threadIdx.x] = emb[v * E + threadIdx.x];
    __syncthreads();
    int g0 = blockIdx.y * 512;
    for (int g = g0 + threadIdx.x; g < g0 + 512; g += blockDim.x) {
        float s = b_ih[g] + b_hh[g];
        const float* w = W_ih + g * E;
#pragma unroll
        for (int e = 0; e < E; e++) s += es[e] * w[e];
        int gate = g >> 10;
        int u = g & (H - 1);
        g_proj[v * G4 + u * 4 + gate] = s;
    }
}

// W_hh -> g_Wph, vectorized: each thread emits one 8B packed chunk (4 k's).
__global__ void permW_hi_kernel(const float* __restrict__ W_hh) {
    int i = blockIdx.x * blockDim.x + threadIdx.x;   // over G4*256 chunks
    int n = i >> 8, c = i & 255;
    int kg = c >> 2, t = c & 3;
    int gate = (((n >> 3) & 1) << 1) | (n & 1);
    int u = ((n >> 4) << 2) | ((n >> 1) & 3);
    const float* src = W_hh + (size_t)(gate * H + u) * H + kg * 16 + 2 * t;
    float2 p0 = *reinterpret_cast<const float2*>(src);      // k, k+1
    float2 p1 = *reinterpret_cast<const float2*>(src + 8);  // k+8, k+9
    __half2 h0 = __floats2half2_rn(p0.x, p0.y);
    __half2 h1 = __floats2half2_rn(p1.x, p1.y);
    uint2 pk = make_uint2(*reinterpret_cast<uint32_t*>(&h0),
                          *reinterpret_cast<uint32_t*>(&h1));
    *reinterpret_cast<uint2*>(g_Wph + (size_t)n * 1024 + c * 4) = pk;
}

// ---------------------------------------------------------------------------
// LSTM step: pre = fp16(h) @ fp16(W)^T, f32 accum. Block 128x128, 8 warps
// (2m x 4n), warp tile 64x32, 64 k16 stages, 6-deep cp.async, 2 CTAs/SM.
__global__ __launch_bounds__(256, 2)
void lstm_step_mma(int t, const int* __restrict__ ids_full, float* __restrict__ out) {
    extern __shared__ __align__(128) uint8_t smem[];
    const uint32_t sb = smem_u32(smem);

    const int tid = threadIdx.x;
    const int wid = tid >> 5;
    const int lane = tid & 31;
    const int gq = lane >> 2;
    const int tq = lane & 3;
    const int wm = wid >> 2;       // 0..1
    const int wn = wid & 3;        // 0..3
    const int m0 = blockIdx.y * 128;
    const int n0 = blockIdx.x * 128;

    const __half* __restrict__ Asrc =
        (t == 0) ? g_h0q : (g_hall + (size_t)(t - 1) * B * 1024);
    const __half* __restrict__ Bsrc = g_Wph;

    auto load_stage = [&](int s) {
        uint32_t buf = sb + (uint32_t)(s % DST) * STAGE_BYTES;
#pragma unroll
        for (int i = 0; i < 2; i++) {
            int c = tid + (i << 8);
            int isB = c >> 8;
            int cc = c & 255;
            int row = cc >> 1, tt = cc & 1;
            const __half* src = isB
                ? (Bsrc + (size_t)(n0 + row) * 1024 + s * 16 + tt * 8)
                : (Asrc + (size_t)(m0 + row) * 1024 + s * 16 + tt * 8);
            uint32_t dst = buf + (uint32_t)(isB << 12) + (uint32_t)(row * 32 + tt * 16);
            asm volatile("cp.async.cg.shared.global [%0], [%1], 16;"
                         :: "r"(dst), "l"(src));
        }
        asm volatile("cp.async.commit_group;" ::: "memory");
    };

    float accM[4][4][4];
#pragma unroll
    for (int i = 0; i < 4; i++)
#pragma unroll
        for (int j = 0; j < 4; j++)
#pragma unroll
            for (int k = 0; k < 4; k++) accM[i][j][k] = 0.f;

#pragma unroll
    for (int s = 0; s < DST - 1; s++) load_stage(s);

    for (int s = 0; s < 64; ++s) {
        asm volatile("cp.async.wait_group %0;" :: "n"(DST - 2) : "memory");
        __syncthreads();

        const uint8_t* buf = smem + (s % DST) * STAGE_BYTES;

        uint2 Bf[4];
#pragma unroll
        for (int ni = 0; ni < 4; ni++) {
            int row = 32 * wn + 8 * ni + gq;
            Bf[ni] = *reinterpret_cast<const uint2*>(buf + 4096 + row * 32 + tq * 8);
        }
#pragma unroll
        for (int mi = 0; mi < 4; mi++) {
            int rowa = 64 * wm + 16 * mi + gq;
            uint2 A0 = *reinterpret_cast<const uint2*>(buf + rowa * 32 + tq * 8);
            uint2 A1 = *reinterpret_cast<const uint2*>(buf + (rowa + 8) * 32 + tq * 8);
#pragma unroll
            for (int ni = 0; ni < 4; ni++) {
                mma_f16_f32(accM[mi][ni], A0.x, A1.x, A0.y, A1.y, Bf[ni].x, Bf[ni].y);
            }
        }

        if (s + DST - 1 < 64) load_stage(s + DST - 1);
        else asm volatile("cp.async.commit_group;" ::: "memory");
    }

    // ---- fused LSTM epilogue ----
    const int* __restrict__ ids = ids_full + t * B;
    __half* __restrict__ hdst = g_hall + (size_t)t * B * 1024;
    const bool last = (t == T_STEPS - 1);
    float* __restrict__ out_h = out + (size_t)T_STEPS * B * V;
    float* __restrict__ out_c = out_h + (size_t)B * H;

#pragma unroll
    for (int mi = 0; mi < 4; mi++) {
#pragma unroll
        for (int rsel = 0; rsel < 2; rsel++) {
            int m = m0 + 64 * wm + 16 * mi + 8 * rsel + gq;
            int id = __ldg(&ids[m]);
            const float4* __restrict__ pv =
                reinterpret_cast<const float4*>(g_proj + (size_t)id * G4);
#pragma unroll
            for (int p = 0; p < 2; p++) {
                int u = ((n0 + 32 * wn + 16 * p) >> 2) + tq;
                float4 P = pv[u];
                int ai = 2 * rsel;
                float pre_i = accM[mi][2*p  ][ai  ] + P.x;
                float pre_f = accM[mi][2*p  ][ai+1] + P.y;
                float pre_g = accM[mi][2*p+1][ai  ] + P.z;
                float pre_o = accM[mi][2*p+1][ai+1] + P.w;
                size_t cx = (size_t)m * H + u;
                float c = sigf(pre_f) * g_c[cx] + sigf(pre_i) * tanha(pre_g);
                g_c[cx] = c;
                float h = sigf(pre_o) * tanha(c);
                hdst[(size_t)m * 1024 + pack_off(u)] = __float2half_rn(h);
                if (last) { out_h[cx] = h; out_c[cx] = c; }
            }
        }
    }
}

// ---------------------------------------------------------------------------
// out_proj slice via HMMA for one timestep's 4096 rows (m_base = t*B).
__global__ __launch_bounds__(256, 2)
void out_proj_mma(int m_base, const float* __restrict__ b_out,
                  float* __restrict__ scores) {
    extern __shared__ __align__(128) uint8_t smem[];
    const uint32_t sb = smem_u32(smem);

    const int tid = threadIdx.x;
    const int wid = tid >> 5;
    const int lane = tid & 31;
    const int gq = lane >> 2;
    const int tq = lane & 3;
    const int m0 = m_base + blockIdx.x * 128;

    auto load_stage = [&](int s) {
        uint32_t buf = sb + (uint32_t)(s % DST) * STAGE_BYTES;
        {   // A: 256 chunks of 16B, 1/thread
            int row = tid >> 1, tt = tid & 1;
            const __half* src = g_hall + (size_t)(m0 + row) * 1024 + s * 16 + tt * 8;
            uint32_t dst = buf + (uint32_t)(row * 32 + tt * 16);
            asm volatile("cp.async.cg.shared.global [%0], [%1], 16;"
                         :: "r"(dst), "l"(src));
        }
        if (tid < 192) {  // B: 96 rows x 2 chunks
            int row = tid >> 1, tt = tid & 1;
            const __half* src = g_Wo + (size_t)row * 1024 + s * 16 + tt * 8;
            uint32_t dst = buf + 4096u + (uint32_t)(row * 32 + tt * 16);
            asm volatile("cp.async.cg.shared.global [%0], [%1], 16;"
                         :: "r"(dst), "l"(src));
        }
        asm volatile("cp.async.commit_group;" ::: "memory");
    };

    float acc[12][4];
#pragma unroll
    for (int i = 0; i < 12; i++)
#pragma unroll
        for (int j = 0; j < 4; j++) acc[i][j] = 0.f;

#pragma unroll
    for (int s = 0; s < DST - 1; s++) load_stage(s);

    for (int s = 0; s < 64; ++s) {
        asm volatile("cp.async.wait_group %0;" :: "n"(DST - 2) : "memory");
        __syncthreads();

        const uint8_t* buf = smem + (s % DST) * STAGE_BYTES;

        int rowa = 16 * wid + gq;
        uint2 A0 = *reinterpret_cast<const uint2*>(buf + rowa * 32 + tq * 8);
        uint2 A1 = *reinterpret_cast<const uint2*>(buf + (rowa + 8) * 32 + tq * 8);
#pragma unroll
        for (int ni = 0; ni < 12; ni++) {
            int row = 8 * ni + gq;
            uint2 Bf = *reinterpret_cast<const uint2*>(buf + 4096 + row * 32 + tq * 8);
            mma_f16_f32(acc[ni], A0.x, A1.x, A0.y, A1.y, Bf.x, Bf.y);
        }

        if (s + DST - 1 < 64) load_stage(s + DST - 1);
        else asm volatile("cp.async.commit_group;" ::: "memory");
    }

#pragma unroll
    for (int rsel = 0; rsel < 2; rsel++) {
        int m = m0 + 16 * wid + 8 * rsel + gq;
#pragma unroll
        for (int ni = 0; ni < 12; ni++) {
            int v = ni * 8 + tq * 2;
            float2 o;
            o.x = acc[ni][2 * rsel]     + __ldg(&b_out[v]);
            o.y = acc[ni][2 * rsel + 1] + __ldg(&b_out[v + 1]);
            *reinterpret_cast<float2*>(scores + (size_t)m * V + v) = o;
        }
    }
}

// ---------------------------------------------------------------------------
extern "C" void kernel_launch(void* const* d_in, const int* in_sizes, int n_in,
                              void* d_out, int out_size) {
    const int*   ids   = (const int*)  d_in[0];
    const float* h0    = (const float*)d_in[1];
    const float* c0    = (const float*)d_in[2];
    const float* emb   = (const float*)d_in[3];
    const float* W_ih  = (const float*)d_in[4];
    const float* W_hh  = (const float*)d_in[5];
    const float* b_ih  = (const float*)d_in[6];
    const float* b_hh  = (const float*)d_in[7];
    const float* W_out = (const float*)d_in[8];
    const float* b_out = (const float*)d_in[9];
    float* out = (float*)d_out;

    // lazy one-time host-side resources (no device memory involved)
    // EXACT R12 topology: one side stream, forked via in-capture events only.
    static cudaStream_t s2 = nullptr;
    static cudaEvent_t evStep[T_STEPS], evJoin;
    if (!s2) {
        cudaStreamCreateWithFlags(&s2, cudaStreamNonBlocking);
        for (int t = 0; t < T_STEPS; ++t)
            cudaEventCreateWithFlags(&evStep[t], cudaEventDisableTiming);
        cudaEventCreateWithFlags(&evJoin, cudaEventDisableTiming);
        cudaFuncSetAttribute(lstm_step_mma, cudaFuncAttributeMaxDynamicSharedMemorySize,
                             SMEM_TOTAL);
        cudaFuncSetAttribute(out_proj_mma, cudaFuncAttributeMaxDynamicSharedMemorySize,
                             SMEM_TOTAL);
    }

    // setup kernels serial on the origin stream (R12-proven)
    init_state_kernel<<<B * H / 256, 256>>>(h0, c0);
    packWo_kernel<<<V * H / 256, 256>>>(W_out);
    vocab_proj_kernel<<<dim3(V, 8), 256>>>(emb, W_ih, b_ih, b_hh);
    permW_hi_kernel<<<G4 * 256 / 256, 256>>>(W_hh);

    dim3 gemm_grid(G4 / 128, B / 128);  // 32 x 32 = 1024 CTAs
    for (int t = 0; t < T_STEPS; ++t) {
        lstm_step_mma<<<gemm_grid, 256, SMEM_TOTAL>>>(t, ids, out);
        // fork: out_proj slice for step t overlaps with step t+1
        cudaEventRecord(evStep[t], 0);
        cudaStreamWaitEvent(s2, evStep[t], 0);
        out_proj_mma<<<B / 128, 256, SMEM_TOTAL, s2>>>(t * B, b_out, out);
    }
    // join side stream back into the captured (default) stream
    cudaEventRecord(evJoin, s2);
    cudaStreamWaitEvent(0, evJoin, 0);
}